// round 6
// baseline (speedup 1.0000x reference)
#include <cuda_runtime.h>
#include <math.h>

#define NN 4096
#define EE 32768
#define ET (EE + NN)
#define HEADS1 8
#define HC1 4096
#define HC2 512

// ---------------- scratch (device globals; no allocation allowed) ----------------
__device__ float g_h1[(size_t)NN * HC1];   // layer1 pre-attention features [N,8,512]
__device__ float g_o1[(size_t)NN * HC1];   // layer1 output (relu)
__device__ float g_h2[NN * HC2];           // layer2 pre-attention features
__device__ float g_o2[NN * HC2];           // layer2 output (relu)
__device__ float g_as[NN * HEADS1];        // alpha_src per (node,head)
__device__ float g_ad[NN * HEADS1];        // alpha_dst per (node,head)
__device__ unsigned g_m[NN * HEADS1];      // segment max, monotone-encoded
__device__ float g_elog[(size_t)ET * HEADS1];
__device__ float g_eexp[(size_t)ET * HEADS1];
__device__ int g_rowptr[NN + 1];
__device__ int g_counts[NN];
__device__ int g_cursor[NN];
__device__ int g_eids[ET];
__device__ int g_srcv[ET];                 // normalized int32 src (incl self-loops)
__device__ int g_dstv[ET];                 // normalized int32 dst
__device__ int g_flag64;                   // 1 if edge_index is int64
__device__ float g_fc1[512 * 512];
__device__ float g_fc2[512 * 128];

// ---- device-side buffer resolution: NO cudaGetSymbolAddress on host ----
#define B_H1 0
#define B_O1 1
#define B_H2 2
#define B_O2 3
#define B_FC1 4
#define B_FC2 5
__device__ __forceinline__ float* bufptr(int b) {
    switch (b) {
        case B_H1: return g_h1;
        case B_O1: return g_o1;
        case B_H2: return g_h2;
        case B_O2: return g_o2;
        case B_FC1: return g_fc1;
        default: return g_fc2;
    }
}

// ------------- float <-> order-preserving uint (for atomicMax on floats) -------------
__device__ __forceinline__ unsigned f2u(float f) {
    unsigned u = __float_as_uint(f);
    return (u & 0x80000000u) ? ~u : (u | 0x80000000u);
}
__device__ __forceinline__ float u2f(unsigned u) {
    return (u & 0x80000000u) ? __uint_as_float(u & 0x7fffffffu)
                             : __uint_as_float(~u);
}

// ---------------- dtype probe: int64 edge_index has all-zero odd int32 words ----------
__global__ void k_detect(const int* __restrict__ raw) {
    __shared__ int s_or;
    if (threadIdx.x == 0) s_or = 0;
    __syncthreads();
    int acc = 0;
    // scan odd words of the first 2*EE int32 words (valid for both dtypes)
    for (int i = threadIdx.x; i < EE; i += blockDim.x) acc |= raw[2 * i + 1];
    if (acc) atomicOr(&s_or, 1);
    __syncthreads();
    if (threadIdx.x == 0) g_flag64 = (s_or == 0) ? 1 : 0;
}

// ---------------- normalize edge list to int32 (+ self-loops) ----------------
__global__ void k_convert(const int* __restrict__ raw) {
    int i = blockIdx.x * blockDim.x + threadIdx.x;
    if (i >= ET) return;
    if (i < EE) {
        if (g_flag64) {  // little-endian low words
            g_srcv[i] = raw[2 * i];
            g_dstv[i] = raw[2 * (EE + i)];
        } else {
            g_srcv[i] = raw[i];
            g_dstv[i] = raw[EE + i];
        }
    } else {
        g_srcv[i] = i - EE;
        g_dstv[i] = i - EE;
    }
}

// ---------------- zeroing kernels (graph-safe) ----------
__global__ void k_zero_csr() {
    int i = blockIdx.x * blockDim.x + threadIdx.x;
    if (i < NN) {
        g_counts[i] = 0;
        g_cursor[i] = 0;
    }
}
__global__ void k_zero_m() {
    int i = blockIdx.x * blockDim.x + threadIdx.x;
    if (i < NN * HEADS1) g_m[i] = 0u;  // encoded -inf
}

// ---------------- CSR build over dst ----------------
__global__ void k_hist() {
    int i = blockIdx.x * blockDim.x + threadIdx.x;
    if (i >= ET) return;
    atomicAdd(&g_counts[g_dstv[i]], 1);
}

__global__ void k_scan() {
    __shared__ int s[1024];
    int t = threadIdx.x;
    int c0 = g_counts[4 * t + 0];
    int c1 = g_counts[4 * t + 1];
    int c2 = g_counts[4 * t + 2];
    int c3 = g_counts[4 * t + 3];
    int sum = c0 + c1 + c2 + c3;
    s[t] = sum;
    __syncthreads();
    for (int off = 1; off < 1024; off <<= 1) {
        int v = (t >= off) ? s[t - off] : 0;
        __syncthreads();
        s[t] += v;
        __syncthreads();
    }
    int excl = s[t] - sum;
    g_rowptr[4 * t + 0] = excl;
    g_rowptr[4 * t + 1] = excl + c0;
    g_rowptr[4 * t + 2] = excl + c0 + c1;
    g_rowptr[4 * t + 3] = excl + c0 + c1 + c2;
    if (t == 1023) g_rowptr[NN] = excl + sum;
}

__global__ void k_scatter() {
    int i = blockIdx.x * blockDim.x + threadIdx.x;
    if (i >= ET) return;
    int dst = g_dstv[i];
    int pos = g_rowptr[dst] + atomicAdd(&g_cursor[dst], 1);
    g_eids[pos] = i;
}

// ---------------- big GEMM: C[M,N] = A[M,K] @ B[K,N], 128x128x16, 8x8/thread ----------------
__global__ __launch_bounds__(256) void k_gemm128(const float* __restrict__ Aext, int Atag,
                                                 const float* __restrict__ B, int Ctag,
                                                 int M, int N, int K) {
    const float* A = Aext ? Aext : bufptr(Atag);
    float* C = bufptr(Ctag);
    __shared__ float As[16][128];
    __shared__ float Bs[16][128];
    int tid = threadIdx.x;
    int tx = tid & 15, ty = tid >> 4;
    int bm = blockIdx.y * 128, bn = blockIdx.x * 128;
    float acc[8][8];
#pragma unroll
    for (int r = 0; r < 8; r++)
#pragma unroll
        for (int c = 0; c < 8; c++) acc[r][c] = 0.f;

    for (int kt = 0; kt < K; kt += 16) {
#pragma unroll
        for (int i = 0; i < 2; i++) {
            int lid = tid + i * 256;
            int arow = lid >> 2, ak4 = lid & 3;
            float4 va = *(const float4*)&A[(size_t)(bm + arow) * K + kt + ak4 * 4];
            As[ak4 * 4 + 0][arow] = va.x;
            As[ak4 * 4 + 1][arow] = va.y;
            As[ak4 * 4 + 2][arow] = va.z;
            As[ak4 * 4 + 3][arow] = va.w;
            int brow = lid >> 5, bc4 = lid & 31;
            float4 vb = *(const float4*)&B[(size_t)(kt + brow) * N + bn + bc4 * 4];
            *(float4*)&Bs[brow][bc4 * 4] = vb;
        }
        __syncthreads();
#pragma unroll
        for (int kk = 0; kk < 16; kk++) {
            float a[8], b[8];
            *(float4*)&a[0] = *(const float4*)&As[kk][ty * 8];
            *(float4*)&a[4] = *(const float4*)&As[kk][ty * 8 + 4];
            *(float4*)&b[0] = *(const float4*)&Bs[kk][tx * 8];
            *(float4*)&b[4] = *(const float4*)&Bs[kk][tx * 8 + 4];
#pragma unroll
            for (int r = 0; r < 8; r++)
#pragma unroll
                for (int c = 0; c < 8; c++) acc[r][c] += a[r] * b[c];
        }
        __syncthreads();
    }
#pragma unroll
    for (int r = 0; r < 8; r++) {
        int m = bm + ty * 8 + r;
#pragma unroll
        for (int c = 0; c < 8; c++) {
            C[(size_t)m * N + bn + tx * 8 + c] = acc[r][c];
        }
    }
}

// ---------------- small GEMM with bias(+relu): 64x64x16, 4x4/thread ----------------
template <bool RELU>
__global__ __launch_bounds__(256) void k_gemm64(int Atag, const float* __restrict__ B,
                                                const float* __restrict__ bias, int Ctag,
                                                int M, int N, int K) {
    const float* A = bufptr(Atag);
    float* C = bufptr(Ctag);
    __shared__ float As[16][64];
    __shared__ float Bs[16][64];
    int tid = threadIdx.x;
    int tx = tid & 15, ty = tid >> 4;
    int bm = blockIdx.y * 64, bn = blockIdx.x * 64;
    float acc[4][4];
#pragma unroll
    for (int r = 0; r < 4; r++)
#pragma unroll
        for (int c = 0; c < 4; c++) acc[r][c] = 0.f;

    for (int kt = 0; kt < K; kt += 16) {
        {
            int arow = tid >> 2, ak4 = tid & 3;
            float4 va = *(const float4*)&A[(size_t)(bm + arow) * K + kt + ak4 * 4];
            As[ak4 * 4 + 0][arow] = va.x;
            As[ak4 * 4 + 1][arow] = va.y;
            As[ak4 * 4 + 2][arow] = va.z;
            As[ak4 * 4 + 3][arow] = va.w;
            int brow = tid >> 4, bc4 = tid & 15;
            float4 vb = *(const float4*)&B[(size_t)(kt + brow) * N + bn + bc4 * 4];
            *(float4*)&Bs[brow][bc4 * 4] = vb;
        }
        __syncthreads();
#pragma unroll
        for (int kk = 0; kk < 16; kk++) {
            float a[4], b[4];
            *(float4*)a = *(const float4*)&As[kk][ty * 4];
            *(float4*)b = *(const float4*)&Bs[kk][tx * 4];
#pragma unroll
            for (int r = 0; r < 4; r++)
#pragma unroll
                for (int c = 0; c < 4; c++) acc[r][c] += a[r] * b[c];
        }
        __syncthreads();
    }
#pragma unroll
    for (int r = 0; r < 4; r++) {
        int m = bm + ty * 4 + r;
#pragma unroll
        for (int c = 0; c < 4; c++) {
            int n = bn + tx * 4 + c;
            float v = acc[r][c] + bias[n];
            if (RELU) v = v > 0.f ? v : 0.f;
            C[(size_t)m * N + n] = v;
        }
    }
}

// ---------------- per-(node,head) attention dot products ----------------
__global__ void k_alpha(int htag, const float* __restrict__ a_s,
                        const float* __restrict__ a_d, int H, int C) {
    const float* h = bufptr(htag);
    int gw = (blockIdx.x * blockDim.x + threadIdx.x) >> 5;
    int lane = threadIdx.x & 31;
    if (gw >= NN * H) return;
    int n = gw / H, hd = gw - n * H;
    const float* hr = h + (size_t)n * H * C + (size_t)hd * C;
    const float* ws = a_s + hd * C;
    const float* wd = a_d + hd * C;
    float s1 = 0.f, s2 = 0.f;
    for (int c = lane; c < C; c += 32) {
        float v = hr[c];
        s1 += v * ws[c];
        s2 += v * wd[c];
    }
#pragma unroll
    for (int o = 16; o; o >>= 1) {
        s1 += __shfl_down_sync(0xffffffffu, s1, o);
        s2 += __shfl_down_sync(0xffffffffu, s2, o);
    }
    if (lane == 0) {
        g_as[gw] = s1;
        g_ad[gw] = s2;
    }
}

// ---------------- edge logits + leaky relu + segment max ----------------
__global__ void k_edge(int H) {
    int i = blockIdx.x * blockDim.x + threadIdx.x;
    if (i >= ET * H) return;
    int e = i / H, hd = i - e * H;
    int src = g_srcv[e], dst = g_dstv[e];
    float v = g_as[src * H + hd] + g_ad[dst * H + hd];
    v = v > 0.f ? v : 0.2f * v;  // leaky_relu(0.2)
    g_elog[i] = v;
    atomicMax(&g_m[dst * H + hd], f2u(v));
}

// ---------------- e = exp(logit - segmax) ----------------
__global__ void k_exp(int H) {
    int i = blockIdx.x * blockDim.x + threadIdx.x;
    if (i >= ET * H) return;
    int e = i / H, hd = i - e * H;
    int dst = g_dstv[e];
    g_eexp[i] = expf(g_elog[i] - u2f(g_m[dst * H + hd]));
}

// ---------------- CSR aggregate: out[dst] = relu(sum_e alpha*h[src] + bias) ----------------
template <int PER, int H>
__global__ __launch_bounds__(256) void k_agg(int htag, const float* __restrict__ bias,
                                             int outtag) {
    const float* h = bufptr(htag);
    float* out = bufptr(outtag);
    const int HC = PER * 256;  // C=512 both layers
    int n = blockIdx.x;
    int tid = threadIdx.x;
    int beg = g_rowptr[n], end = g_rowptr[n + 1];

    __shared__ float s_inv[H];
    if (tid < H) {
        float s = 0.f;
        for (int idx = beg; idx < end; ++idx) {
            int eid = g_eids[idx];
            s += g_eexp[eid * H + tid];
        }
        s_inv[tid] = 1.f / s;
    }
    __syncthreads();

    float acc[PER];
#pragma unroll
    for (int j = 0; j < PER; j++) acc[j] = 0.f;

    for (int idx = beg; idx < end; ++idx) {
        int eid = g_eids[idx];
        int src = g_srcv[eid];
        const float* hr = h + (size_t)src * HC;
        float aH[H];
#pragma unroll
        for (int hd = 0; hd < H; hd++) aH[hd] = g_eexp[eid * H + hd] * s_inv[hd];
#pragma unroll
        for (int j = 0; j < PER; j++) acc[j] += aH[j >> 1] * hr[tid + j * 256];
    }
#pragma unroll
    for (int j = 0; j < PER; j++) {
        int c = tid + j * 256;
        float v = acc[j] + bias[c];
        out[(size_t)n * HC + c] = v > 0.f ? v : 0.f;
    }
}

// ---------------- fc3 (tiny, N=10) ----------------
__global__ void k_fc3(int Atag, const float* __restrict__ W,
                      const float* __restrict__ b, float* __restrict__ out) {
    const float* A = bufptr(Atag);
    int i = blockIdx.x * blockDim.x + threadIdx.x;
    if (i >= 512 * 10) return;
    int m = i / 10, n = i - m * 10;
    float s = b[n];
#pragma unroll 8
    for (int k = 0; k < 128; k++) s += A[m * 128 + k] * W[k * 10 + n];
    out[i] = s;
}

extern "C" void kernel_launch(void* const* d_in, const int* in_sizes, int n_in,
                              void* d_out, int out_size) {
    const float* x = (const float*)d_in[0];
    const int* ei_raw = (const int*)d_in[1];  // dtype probed device-side (int32 vs int64)
    // d_in[2] = edge_attr, unused (GATConv built without edge_dim)
    const float* W1 = (const float*)d_in[3];
    const float* as1 = (const float*)d_in[4];
    const float* ad1 = (const float*)d_in[5];
    const float* b1 = (const float*)d_in[6];
    const float* W2 = (const float*)d_in[7];
    const float* as2 = (const float*)d_in[8];
    const float* ad2 = (const float*)d_in[9];
    const float* b2 = (const float*)d_in[10];
    const float* fc1w = (const float*)d_in[11];
    const float* fc1b = (const float*)d_in[12];
    const float* fc2w = (const float*)d_in[13];
    const float* fc2b = (const float*)d_in[14];
    const float* fc3w = (const float*)d_in[15];
    const float* fc3b = (const float*)d_in[16];
    float* out = (float*)d_out;

    // ---- normalize edge list + CSR build ----
    k_detect<<<1, 1024>>>(ei_raw);
    k_convert<<<(ET + 255) / 256, 256>>>(ei_raw);
    k_zero_csr<<<(NN + 255) / 256, 256>>>();
    k_hist<<<(ET + 255) / 256, 256>>>();
    k_scan<<<1, 1024>>>();
    k_scatter<<<(ET + 255) / 256, 256>>>();

    // ---- layer 1 ----
    k_gemm128<<<dim3(HC1 / 128, NN / 128), 256>>>(x, -1, W1, B_H1, NN, HC1, 128);
    k_alpha<<<(NN * HEADS1 * 32) / 256, 256>>>(B_H1, as1, ad1, HEADS1, 512);
    k_zero_m<<<(NN * HEADS1 + 255) / 256, 256>>>();
    k_edge<<<(ET * HEADS1 + 255) / 256, 256>>>(HEADS1);
    k_exp<<<(ET * HEADS1 + 255) / 256, 256>>>(HEADS1);
    k_agg<16, 8><<<NN, 256>>>(B_H1, b1, B_O1);

    // ---- layer 2 ----
    k_gemm128<<<dim3(HC2 / 128, NN / 128), 256>>>(nullptr, B_O1, W2, B_H2, NN, HC2, HC1);
    k_alpha<<<(NN * 32 + 255) / 256, 256>>>(B_H2, as2, ad2, 1, 512);
    k_zero_m<<<(NN * HEADS1 + 255) / 256, 256>>>();
    k_edge<<<(ET + 255) / 256, 256>>>(1);
    k_exp<<<(ET + 255) / 256, 256>>>(1);
    k_agg<2, 1><<<NN, 256>>>(B_H2, b2, B_O2);

    // ---- MLP head: g_o2 viewed as [512, 4096] ----
    k_gemm64<true><<<dim3(512 / 64, 512 / 64), 256>>>(B_O2, fc1w, fc1b, B_FC1, 512, 512, HC1);
    k_gemm64<true><<<dim3(128 / 64, 512 / 64), 256>>>(B_FC1, fc2w, fc2b, B_FC2, 512, 128, 512);
    k_fc3<<<(512 * 10 + 255) / 256, 256>>>(B_FC2, fc3w, fc3b, out);
}

// round 7
// speedup vs baseline: 1.9525x; 1.9525x over previous
#include <cuda_runtime.h>
#include <math.h>

#define NN 4096
#define EE 32768
#define ET (EE + NN)
#define HEADS1 8
#define HC1 4096
#define HC2 512
#define FC1_SPLITS 8

// ---------------- scratch (device globals; no allocation allowed) ----------------
__device__ float g_h1[(size_t)NN * HC1];   // layer1 pre-attention features [N,8,512]
__device__ float g_o1[(size_t)NN * HC1];   // layer1 output (relu)
__device__ float g_h2[NN * HC2];           // layer2 pre-attention features
__device__ float g_o2[NN * HC2];           // layer2 output (relu)
__device__ float g_as[NN * HEADS1];        // alpha_src per (node,head)
__device__ float g_ad[NN * HEADS1];        // alpha_dst per (node,head)
__device__ unsigned g_m[NN * HEADS1];      // segment max, monotone-encoded
__device__ float g_elog[(size_t)ET * HEADS1];
__device__ float g_eexp[(size_t)ET * HEADS1];
__device__ int g_rowptr[NN + 1];
__device__ int g_counts[NN];
__device__ int g_cursor[NN];
__device__ int g_eids[ET];
__device__ int g_srcv[ET];                 // normalized int32 src (incl self-loops)
__device__ int g_dstv[ET];                 // normalized int32 dst
__device__ int g_flag64;                   // 1 if edge_index is int64
__device__ float g_fc1[512 * 512];
__device__ float g_fc2[512 * 128];
__device__ float g_fcp[FC1_SPLITS * 512 * 512];  // fc1 split-K partials

// ---- device-side buffer resolution: NO cudaGetSymbolAddress on host ----
#define B_H1 0
#define B_O1 1
#define B_H2 2
#define B_O2 3
#define B_FC1 4
#define B_FC2 5
#define B_FCP 6
__device__ __forceinline__ float* bufptr(int b) {
    switch (b) {
        case B_H1: return g_h1;
        case B_O1: return g_o1;
        case B_H2: return g_h2;
        case B_O2: return g_o2;
        case B_FC1: return g_fc1;
        case B_FC2: return g_fc2;
        default: return g_fcp;
    }
}

// ------------- float <-> order-preserving uint (for atomicMax on floats) -------------
__device__ __forceinline__ unsigned f2u(float f) {
    unsigned u = __float_as_uint(f);
    return (u & 0x80000000u) ? ~u : (u | 0x80000000u);
}
__device__ __forceinline__ float u2f(unsigned u) {
    return (u & 0x80000000u) ? __uint_as_float(u & 0x7fffffffu)
                             : __uint_as_float(~u);
}

// ------------- tf32 helpers -------------
__device__ __forceinline__ unsigned f2tf32(float f) {
    unsigned r;
    asm("cvt.rna.tf32.f32 %0, %1;" : "=r"(r) : "f"(f));
    return r;
}
__device__ __forceinline__ void mma_tf32(float* d, unsigned a0, unsigned a1, unsigned a2,
                                         unsigned a3, unsigned b0, unsigned b1) {
    asm volatile(
        "mma.sync.aligned.m16n8k8.row.col.f32.tf32.tf32.f32 "
        "{%0,%1,%2,%3}, {%4,%5,%6,%7}, {%8,%9}, {%0,%1,%2,%3};\n"
        : "+f"(d[0]), "+f"(d[1]), "+f"(d[2]), "+f"(d[3])
        : "r"(a0), "r"(a1), "r"(a2), "r"(a3), "r"(b0), "r"(b1));
}

// ---------------- dtype probe: int64 edge_index has all-zero odd int32 words ----------
__global__ void k_detect(const int* __restrict__ raw) {
    __shared__ int s_or;
    if (threadIdx.x == 0) s_or = 0;
    __syncthreads();
    int acc = 0;
    for (int i = threadIdx.x; i < EE; i += blockDim.x) acc |= raw[2 * i + 1];
    if (acc) atomicOr(&s_or, 1);
    __syncthreads();
    if (threadIdx.x == 0) g_flag64 = (s_or == 0) ? 1 : 0;
}

// ---------------- normalize edge list to int32 (+ self-loops) ----------------
__global__ void k_convert(const int* __restrict__ raw) {
    int i = blockIdx.x * blockDim.x + threadIdx.x;
    if (i >= ET) return;
    if (i < EE) {
        if (g_flag64) {
            g_srcv[i] = raw[2 * i];
            g_dstv[i] = raw[2 * (EE + i)];
        } else {
            g_srcv[i] = raw[i];
            g_dstv[i] = raw[EE + i];
        }
    } else {
        g_srcv[i] = i - EE;
        g_dstv[i] = i - EE;
    }
}

// ---------------- zeroing kernels (graph-safe) ----------
__global__ void k_zero_csr() {
    int i = blockIdx.x * blockDim.x + threadIdx.x;
    if (i < NN) {
        g_counts[i] = 0;
        g_cursor[i] = 0;
    }
}
__global__ void k_zero_m() {
    int i = blockIdx.x * blockDim.x + threadIdx.x;
    if (i < NN * HEADS1) g_m[i] = 0u;
}

// ---------------- CSR build over dst ----------------
__global__ void k_hist() {
    int i = blockIdx.x * blockDim.x + threadIdx.x;
    if (i >= ET) return;
    atomicAdd(&g_counts[g_dstv[i]], 1);
}

__global__ void k_scan() {
    __shared__ int s[1024];
    int t = threadIdx.x;
    int c0 = g_counts[4 * t + 0];
    int c1 = g_counts[4 * t + 1];
    int c2 = g_counts[4 * t + 2];
    int c3 = g_counts[4 * t + 3];
    int sum = c0 + c1 + c2 + c3;
    s[t] = sum;
    __syncthreads();
    for (int off = 1; off < 1024; off <<= 1) {
        int v = (t >= off) ? s[t - off] : 0;
        __syncthreads();
        s[t] += v;
        __syncthreads();
    }
    int excl = s[t] - sum;
    g_rowptr[4 * t + 0] = excl;
    g_rowptr[4 * t + 1] = excl + c0;
    g_rowptr[4 * t + 2] = excl + c0 + c1;
    g_rowptr[4 * t + 3] = excl + c0 + c1 + c2;
    if (t == 1023) g_rowptr[NN] = excl + sum;
}

__global__ void k_scatter() {
    int i = blockIdx.x * blockDim.x + threadIdx.x;
    if (i >= ET) return;
    int dst = g_dstv[i];
    int pos = g_rowptr[dst] + atomicAdd(&g_cursor[dst], 1);
    g_eids[pos] = i;
}

// ---------------- tf32 tensor-core GEMM: 128x128 tile, 8 warps, m16n8k8 ----------------
// C[M,N] (+ blockIdx.z*M*N for split-K) = A[M, lda-chunk] @ B[chunk, N]
__global__ __launch_bounds__(256) void k_mm_tf32(const float* __restrict__ Aext, int Atag,
                                                 const float* __restrict__ Bsrc, int Ctag,
                                                 int M, int N, int Kc, int lda) {
    const float* A = Aext ? Aext : bufptr(Atag);
    float* C = bufptr(Ctag) + (size_t)blockIdx.z * M * N;
    int koff = blockIdx.z * Kc;
    __shared__ unsigned As[16][136];
    __shared__ unsigned Bs[16][136];
    int tid = threadIdx.x;
    int lane = tid & 31, wid = tid >> 5;
    int wm = (wid >> 2) * 64, wn = (wid & 3) * 32;
    int bm = blockIdx.y * 128, bn = blockIdx.x * 128;
    int g = lane >> 2, t = lane & 3;

    float acc[4][4][4];
#pragma unroll
    for (int i = 0; i < 4; i++)
#pragma unroll
        for (int j = 0; j < 4; j++)
#pragma unroll
            for (int r = 0; r < 4; r++) acc[i][j][r] = 0.f;

    for (int kt = 0; kt < Kc; kt += 16) {
#pragma unroll
        for (int i = 0; i < 2; i++) {
            int lid = tid + i * 256;
            int arow = lid >> 2, ak4 = lid & 3;
            float4 va = *(const float4*)&A[(size_t)(bm + arow) * lda + koff + kt + ak4 * 4];
            As[ak4 * 4 + 0][arow] = f2tf32(va.x);
            As[ak4 * 4 + 1][arow] = f2tf32(va.y);
            As[ak4 * 4 + 2][arow] = f2tf32(va.z);
            As[ak4 * 4 + 3][arow] = f2tf32(va.w);
            int brow = lid >> 5, bc4 = lid & 31;
            float4 vb = *(const float4*)&Bsrc[(size_t)(koff + kt + brow) * N + bn + bc4 * 4];
            Bs[brow][bc4 * 4 + 0] = f2tf32(vb.x);
            Bs[brow][bc4 * 4 + 1] = f2tf32(vb.y);
            Bs[brow][bc4 * 4 + 2] = f2tf32(vb.z);
            Bs[brow][bc4 * 4 + 3] = f2tf32(vb.w);
        }
        __syncthreads();
#pragma unroll
        for (int ks = 0; ks < 16; ks += 8) {
            unsigned bfr[4][2];
#pragma unroll
            for (int j = 0; j < 4; j++) {
                bfr[j][0] = Bs[ks + t][wn + j * 8 + g];
                bfr[j][1] = Bs[ks + t + 4][wn + j * 8 + g];
            }
#pragma unroll
            for (int i = 0; i < 4; i++) {
                int mrow = wm + i * 16 + g;
                unsigned a0 = As[ks + t][mrow];
                unsigned a1 = As[ks + t][mrow + 8];
                unsigned a2 = As[ks + t + 4][mrow];
                unsigned a3 = As[ks + t + 4][mrow + 8];
#pragma unroll
                for (int j = 0; j < 4; j++)
                    mma_tf32(acc[i][j], a0, a1, a2, a3, bfr[j][0], bfr[j][1]);
            }
        }
        __syncthreads();
    }
#pragma unroll
    for (int i = 0; i < 4; i++) {
        int row = bm + wm + i * 16 + g;
#pragma unroll
        for (int j = 0; j < 4; j++) {
            int col = bn + wn + j * 8 + t * 2;
            *(float2*)&C[(size_t)row * N + col] = make_float2(acc[i][j][0], acc[i][j][1]);
            *(float2*)&C[(size_t)(row + 8) * N + col] = make_float2(acc[i][j][2], acc[i][j][3]);
        }
    }
}

// ---------------- fc1 split-K reduce + bias + relu ----------------
__global__ void k_fcreduce(const float* __restrict__ bias) {
    int i = blockIdx.x * blockDim.x + threadIdx.x;
    if (i >= 512 * 512) return;
    float s = bias[i & 511];
#pragma unroll
    for (int p = 0; p < FC1_SPLITS; p++) s += g_fcp[p * 512 * 512 + i];
    g_fc1[i] = s > 0.f ? s : 0.f;
}

// ---------------- small GEMM with bias(+relu): 64x64x16, 4x4/thread (fc2) ---------------
template <bool RELU>
__global__ __launch_bounds__(256) void k_gemm64(int Atag, const float* __restrict__ B,
                                                const float* __restrict__ bias, int Ctag,
                                                int M, int N, int K) {
    const float* A = bufptr(Atag);
    float* C = bufptr(Ctag);
    __shared__ float As[16][64];
    __shared__ float Bs[16][64];
    int tid = threadIdx.x;
    int tx = tid & 15, ty = tid >> 4;
    int bm = blockIdx.y * 64, bn = blockIdx.x * 64;
    float acc[4][4];
#pragma unroll
    for (int r = 0; r < 4; r++)
#pragma unroll
        for (int c = 0; c < 4; c++) acc[r][c] = 0.f;

    for (int kt = 0; kt < K; kt += 16) {
        {
            int arow = tid >> 2, ak4 = tid & 3;
            float4 va = *(const float4*)&A[(size_t)(bm + arow) * K + kt + ak4 * 4];
            As[ak4 * 4 + 0][arow] = va.x;
            As[ak4 * 4 + 1][arow] = va.y;
            As[ak4 * 4 + 2][arow] = va.z;
            As[ak4 * 4 + 3][arow] = va.w;
            int brow = tid >> 4, bc4 = tid & 15;
            float4 vb = *(const float4*)&B[(size_t)(kt + brow) * N + bn + bc4 * 4];
            *(float4*)&Bs[brow][bc4 * 4] = vb;
        }
        __syncthreads();
#pragma unroll
        for (int kk = 0; kk < 16; kk++) {
            float a[4], b[4];
            *(float4*)a = *(const float4*)&As[kk][ty * 4];
            *(float4*)b = *(const float4*)&Bs[kk][tx * 4];
#pragma unroll
            for (int r = 0; r < 4; r++)
#pragma unroll
                for (int c = 0; c < 4; c++) acc[r][c] += a[r] * b[c];
        }
        __syncthreads();
    }
#pragma unroll
    for (int r = 0; r < 4; r++) {
        int m = bm + ty * 4 + r;
#pragma unroll
        for (int c = 0; c < 4; c++) {
            int n = bn + tx * 4 + c;
            float v = acc[r][c] + bias[n];
            if (RELU) v = v > 0.f ? v : 0.f;
            C[(size_t)m * N + n] = v;
        }
    }
}

// ---------------- per-(node,head) attention dot products ----------------
__global__ void k_alpha(int htag, const float* __restrict__ a_s,
                        const float* __restrict__ a_d, int H, int C) {
    const float* h = bufptr(htag);
    int gw = (blockIdx.x * blockDim.x + threadIdx.x) >> 5;
    int lane = threadIdx.x & 31;
    if (gw >= NN * H) return;
    int n = gw / H, hd = gw - n * H;
    const float* hr = h + (size_t)n * H * C + (size_t)hd * C;
    const float* ws = a_s + hd * C;
    const float* wd = a_d + hd * C;
    float s1 = 0.f, s2 = 0.f;
    for (int c = lane; c < C; c += 32) {
        float v = hr[c];
        s1 += v * ws[c];
        s2 += v * wd[c];
    }
#pragma unroll
    for (int o = 16; o; o >>= 1) {
        s1 += __shfl_down_sync(0xffffffffu, s1, o);
        s2 += __shfl_down_sync(0xffffffffu, s2, o);
    }
    if (lane == 0) {
        g_as[gw] = s1;
        g_ad[gw] = s2;
    }
}

// ---------------- edge logits + leaky relu + segment max ----------------
__global__ void k_edge(int H) {
    int i = blockIdx.x * blockDim.x + threadIdx.x;
    if (i >= ET * H) return;
    int e = i / H, hd = i - e * H;
    int src = g_srcv[e], dst = g_dstv[e];
    float v = g_as[src * H + hd] + g_ad[dst * H + hd];
    v = v > 0.f ? v : 0.2f * v;
    g_elog[i] = v;
    atomicMax(&g_m[dst * H + hd], f2u(v));
}

// ---------------- e = exp(logit - segmax) ----------------
__global__ void k_exp(int H) {
    int i = blockIdx.x * blockDim.x + threadIdx.x;
    if (i >= ET * H) return;
    int e = i / H, hd = i - e * H;
    int dst = g_dstv[e];
    g_eexp[i] = expf(g_elog[i] - u2f(g_m[dst * H + hd]));
}

// ---------------- CSR aggregate: out[dst] = relu(sum_e alpha*h[src] + bias) ----------------
template <int PER, int H>
__global__ __launch_bounds__(256) void k_agg(int htag, const float* __restrict__ bias,
                                             int outtag) {
    const float* h = bufptr(htag);
    float* out = bufptr(outtag);
    const int HC = PER * 256;
    int n = blockIdx.x;
    int tid = threadIdx.x;
    int beg = g_rowptr[n], end = g_rowptr[n + 1];

    __shared__ float s_inv[H];
    if (tid < H) {
        float s = 0.f;
        for (int idx = beg; idx < end; ++idx) {
            int eid = g_eids[idx];
            s += g_eexp[eid * H + tid];
        }
        s_inv[tid] = 1.f / s;
    }
    __syncthreads();

    float acc[PER];
#pragma unroll
    for (int j = 0; j < PER; j++) acc[j] = 0.f;

    for (int idx = beg; idx < end; ++idx) {
        int eid = g_eids[idx];
        int src = g_srcv[eid];
        const float* hr = h + (size_t)src * HC;
        float aH[H];
#pragma unroll
        for (int hd = 0; hd < H; hd++) aH[hd] = g_eexp[eid * H + hd] * s_inv[hd];
#pragma unroll
        for (int j = 0; j < PER; j++) acc[j] += aH[j >> 1] * hr[tid + j * 256];
    }
#pragma unroll
    for (int j = 0; j < PER; j++) {
        int c = tid + j * 256;
        float v = acc[j] + bias[c];
        out[(size_t)n * HC + c] = v > 0.f ? v : 0.f;
    }
}

// ---------------- fc3 (tiny, N=10) ----------------
__global__ void k_fc3(int Atag, const float* __restrict__ W,
                      const float* __restrict__ b, float* __restrict__ out) {
    const float* A = bufptr(Atag);
    int i = blockIdx.x * blockDim.x + threadIdx.x;
    if (i >= 512 * 10) return;
    int m = i / 10, n = i - m * 10;
    float s = b[n];
#pragma unroll 8
    for (int k = 0; k < 128; k++) s += A[m * 128 + k] * W[k * 10 + n];
    out[i] = s;
}

extern "C" void kernel_launch(void* const* d_in, const int* in_sizes, int n_in,
                              void* d_out, int out_size) {
    const float* x = (const float*)d_in[0];
    const int* ei_raw = (const int*)d_in[1];
    const float* W1 = (const float*)d_in[3];
    const float* as1 = (const float*)d_in[4];
    const float* ad1 = (const float*)d_in[5];
    const float* b1 = (const float*)d_in[6];
    const float* W2 = (const float*)d_in[7];
    const float* as2 = (const float*)d_in[8];
    const float* ad2 = (const float*)d_in[9];
    const float* b2 = (const float*)d_in[10];
    const float* fc1w = (const float*)d_in[11];
    const float* fc1b = (const float*)d_in[12];
    const float* fc2w = (const float*)d_in[13];
    const float* fc2b = (const float*)d_in[14];
    const float* fc3w = (const float*)d_in[15];
    const float* fc3b = (const float*)d_in[16];
    float* out = (float*)d_out;

    // ---- normalize edge list + CSR build ----
    k_detect<<<1, 1024>>>(ei_raw);
    k_convert<<<(ET + 255) / 256, 256>>>(ei_raw);
    k_zero_csr<<<(NN + 255) / 256, 256>>>();
    k_hist<<<(ET + 255) / 256, 256>>>();
    k_scan<<<1, 1024>>>();
    k_scatter<<<(ET + 255) / 256, 256>>>();

    // ---- layer 1 ----
    k_mm_tf32<<<dim3(HC1 / 128, NN / 128, 1), 256>>>(x, -1, W1, B_H1, NN, HC1, 128, 128);
    k_alpha<<<(NN * HEADS1 * 32) / 256, 256>>>(B_H1, as1, ad1, HEADS1, 512);
    k_zero_m<<<(NN * HEADS1 + 255) / 256, 256>>>();
    k_edge<<<(ET * HEADS1 + 255) / 256, 256>>>(HEADS1);
    k_exp<<<(ET * HEADS1 + 255) / 256, 256>>>(HEADS1);
    k_agg<16, 8><<<NN, 256>>>(B_H1, b1, B_O1);

    // ---- layer 2 ----
    k_mm_tf32<<<dim3(HC2 / 128, NN / 128, 1), 256>>>(nullptr, B_O1, W2, B_H2, NN, HC2,
                                                     HC1, HC1);
    k_alpha<<<(NN * 32 + 255) / 256, 256>>>(B_H2, as2, ad2, 1, 512);
    k_zero_m<<<(NN * HEADS1 + 255) / 256, 256>>>();
    k_edge<<<(ET + 255) / 256, 256>>>(1);
    k_exp<<<(ET + 255) / 256, 256>>>(1);
    k_agg<2, 1><<<NN, 256>>>(B_H2, b2, B_O2);

    // ---- MLP head: g_o2 viewed as [512, 4096] ----
    k_mm_tf32<<<dim3(512 / 128, 512 / 128, FC1_SPLITS), 256>>>(
        nullptr, B_O2, fc1w, B_FCP, 512, 512, HC1 / FC1_SPLITS, HC1);
    k_fcreduce<<<(512 * 512 + 255) / 256, 256>>>(fc1b);
    k_gemm64<true><<<dim3(128 / 64, 512 / 64), 256>>>(B_FC1, fc2w, fc2b, B_FC2, 512, 128, 512);
    k_fc3<<<(512 * 10 + 255) / 256, 256>>>(B_FC2, fc3w, fc3b, out);
}

// round 8
// speedup vs baseline: 2.8245x; 1.4466x over previous
#include <cuda_runtime.h>
#include <math.h>

#define NN 4096
#define EE 32768
#define ET (EE + NN)
#define HEADS1 8
#define HC1 4096
#define HC2 512
#define FC1_SPLITS 8

// ---------------- scratch (device globals; no allocation allowed) ----------------
__device__ float g_h1[(size_t)NN * HC1];
__device__ float g_o1[(size_t)NN * HC1];
__device__ float g_h2[NN * HC2];
__device__ float g_o2[NN * HC2];
__device__ float g_as[NN * HEADS1];
__device__ float g_ad[NN * HEADS1];
__device__ unsigned g_m[NN * HEADS1];
__device__ float g_elog[(size_t)ET * HEADS1];
__device__ float g_eexp[(size_t)ET * HEADS1];
__device__ int g_rowptr[NN + 1];
__device__ int g_counts[NN];
__device__ int g_cursor[NN];
__device__ int g_eids[ET];
__device__ int g_srcv[ET];
__device__ int g_dstv[ET];
__device__ int g_flag64;
__device__ float g_fc1[512 * 512];
__device__ float g_fc2[512 * 128];
__device__ float g_fcp[FC1_SPLITS * 512 * 512];
__device__ float g_gp2[2 * NN * HC2];  // GEMM2 split-K partials

#define B_H1 0
#define B_O1 1
#define B_H2 2
#define B_O2 3
#define B_FC1 4
#define B_FC2 5
#define B_FCP 6
#define B_GP2 7
__device__ __forceinline__ float* bufptr(int b) {
    switch (b) {
        case B_H1: return g_h1;
        case B_O1: return g_o1;
        case B_H2: return g_h2;
        case B_O2: return g_o2;
        case B_FC1: return g_fc1;
        case B_FC2: return g_fc2;
        case B_FCP: return g_fcp;
        default: return g_gp2;
    }
}

// ------------- float <-> order-preserving uint -------------
__device__ __forceinline__ unsigned f2u(float f) {
    unsigned u = __float_as_uint(f);
    return (u & 0x80000000u) ? ~u : (u | 0x80000000u);
}
__device__ __forceinline__ float u2f(unsigned u) {
    return (u & 0x80000000u) ? __uint_as_float(u & 0x7fffffffu)
                             : __uint_as_float(~u);
}

// ------------- tf32 + cp.async helpers -------------
__device__ __forceinline__ unsigned f2tf32(float f) {
    unsigned r;
    asm("cvt.rna.tf32.f32 %0, %1;" : "=r"(r) : "f"(f));
    return r;
}
__device__ __forceinline__ void mma_tf32(float* d, unsigned a0, unsigned a1, unsigned a2,
                                         unsigned a3, unsigned b0, unsigned b1) {
    asm volatile(
        "mma.sync.aligned.m16n8k8.row.col.f32.tf32.tf32.f32 "
        "{%0,%1,%2,%3}, {%4,%5,%6,%7}, {%8,%9}, {%0,%1,%2,%3};\n"
        : "+f"(d[0]), "+f"(d[1]), "+f"(d[2]), "+f"(d[3])
        : "r"(a0), "r"(a1), "r"(a2), "r"(a3), "r"(b0), "r"(b1));
}
__device__ __forceinline__ void cpasync16(void* s, const void* g) {
    unsigned sa = (unsigned)__cvta_generic_to_shared(s);
    asm volatile("cp.async.ca.shared.global [%0], [%1], 16;\n" ::"r"(sa), "l"(g));
}
__device__ __forceinline__ void cp_commit() {
    asm volatile("cp.async.commit_group;\n");
}
__device__ __forceinline__ void cp_wait1() {
    asm volatile("cp.async.wait_group 1;\n");
}
__device__ __forceinline__ void cp_wait0() {
    asm volatile("cp.async.wait_group 0;\n");
}

// ---------------- dtype probe ----------
__global__ void k_detect(const int* __restrict__ raw) {
    __shared__ int s_or;
    if (threadIdx.x == 0) s_or = 0;
    __syncthreads();
    int acc = 0;
    for (int i = threadIdx.x; i < EE; i += blockDim.x) acc |= raw[2 * i + 1];
    if (acc) atomicOr(&s_or, 1);
    __syncthreads();
    if (threadIdx.x == 0) g_flag64 = (s_or == 0) ? 1 : 0;
}

__global__ void k_convert(const int* __restrict__ raw) {
    int i = blockIdx.x * blockDim.x + threadIdx.x;
    if (i >= ET) return;
    if (i < EE) {
        if (g_flag64) {
            g_srcv[i] = raw[2 * i];
            g_dstv[i] = raw[2 * (EE + i)];
        } else {
            g_srcv[i] = raw[i];
            g_dstv[i] = raw[EE + i];
        }
    } else {
        g_srcv[i] = i - EE;
        g_dstv[i] = i - EE;
    }
}

__global__ void k_zero_csr() {
    int i = blockIdx.x * blockDim.x + threadIdx.x;
    if (i < NN) {
        g_counts[i] = 0;
        g_cursor[i] = 0;
    }
}
__global__ void k_zero_m() {
    int i = blockIdx.x * blockDim.x + threadIdx.x;
    if (i < NN * HEADS1) g_m[i] = 0u;
}

__global__ void k_hist() {
    int i = blockIdx.x * blockDim.x + threadIdx.x;
    if (i >= ET) return;
    atomicAdd(&g_counts[g_dstv[i]], 1);
}

__global__ void k_scan() {
    __shared__ int s[1024];
    int t = threadIdx.x;
    int c0 = g_counts[4 * t + 0];
    int c1 = g_counts[4 * t + 1];
    int c2 = g_counts[4 * t + 2];
    int c3 = g_counts[4 * t + 3];
    int sum = c0 + c1 + c2 + c3;
    s[t] = sum;
    __syncthreads();
    for (int off = 1; off < 1024; off <<= 1) {
        int v = (t >= off) ? s[t - off] : 0;
        __syncthreads();
        s[t] += v;
        __syncthreads();
    }
    int excl = s[t] - sum;
    g_rowptr[4 * t + 0] = excl;
    g_rowptr[4 * t + 1] = excl + c0;
    g_rowptr[4 * t + 2] = excl + c0 + c1;
    g_rowptr[4 * t + 3] = excl + c0 + c1 + c2;
    if (t == 1023) g_rowptr[NN] = excl + sum;
}

__global__ void k_scatter() {
    int i = blockIdx.x * blockDim.x + threadIdx.x;
    if (i >= ET) return;
    int dst = g_dstv[i];
    int pos = g_rowptr[dst] + atomicAdd(&g_cursor[dst], 1);
    g_eids[pos] = i;
}

// ---------------- pipelined tf32 GEMM: 128x128 tile, cp.async double buffer -----------
// C[M,N] (+ blockIdx.z*M*N) = A[M, koff..koff+Kc] @ B[koff..][N]
__global__ __launch_bounds__(256) void k_mm_tf32(const float* __restrict__ Aext, int Atag,
                                                 const float* __restrict__ Bsrc, int Ctag,
                                                 int M, int N, int Kc, int lda) {
    const float* A = Aext ? Aext : bufptr(Atag);
    float* C = bufptr(Ctag) + (size_t)blockIdx.z * M * N;
    int koff = blockIdx.z * Kc;
    __shared__ float As[2][128][20];   // m-major, stride 20 -> conflict-free frags
    __shared__ float Bs[2][16][136];   // k-major, stride 136 -> conflict-free frags
    int tid = threadIdx.x;
    int lane = tid & 31, wid = tid >> 5;
    int wm = (wid >> 2) * 64, wn = (wid & 3) * 32;
    int bm = blockIdx.y * 128, bn = blockIdx.x * 128;
    int g = lane >> 2, t = lane & 3;

    float acc[4][4][4];
#pragma unroll
    for (int i = 0; i < 4; i++)
#pragma unroll
        for (int j = 0; j < 4; j++)
#pragma unroll
            for (int r = 0; r < 4; r++) acc[i][j][r] = 0.f;

    const int NIT = Kc / 16;
    int arow = tid >> 1, ak4 = tid & 1;  // 128 rows x 2 float4 halves... (see below)
    // A tile: 128 rows x 16 k = 512 float4; 256 threads -> 2 each
    // B tile: 16 rows x 128 n = 512 float4; 256 threads -> 2 each
#define LOAD_TILE(it, buf)                                                              \
    {                                                                                   \
        int kt = (it) * 16;                                                             \
        _Pragma("unroll") for (int i = 0; i < 2; i++) {                                 \
            int lid = tid + i * 256;                                                    \
            int ar = lid >> 2, a4 = lid & 3;                                            \
            cpasync16(&As[buf][ar][a4 * 4],                                             \
                      &A[(size_t)(bm + ar) * lda + koff + kt + a4 * 4]);                \
            int br = lid >> 5, b4 = lid & 31;                                           \
            cpasync16(&Bs[buf][br][b4 * 4],                                             \
                      &Bsrc[(size_t)(koff + kt + br) * N + bn + b4 * 4]);               \
        }                                                                               \
    }

    LOAD_TILE(0, 0);
    cp_commit();

    for (int it = 0; it < NIT; it++) {
        int cb = it & 1;
        if (it + 1 < NIT) {
            LOAD_TILE(it + 1, cb ^ 1);
            cp_commit();
            cp_wait1();
        } else {
            cp_wait0();
        }
        __syncthreads();
#pragma unroll
        for (int ks = 0; ks < 16; ks += 8) {
            unsigned bfr[4][2];
#pragma unroll
            for (int j = 0; j < 4; j++) {
                bfr[j][0] = f2tf32(Bs[cb][ks + t][wn + j * 8 + g]);
                bfr[j][1] = f2tf32(Bs[cb][ks + t + 4][wn + j * 8 + g]);
            }
#pragma unroll
            for (int i = 0; i < 4; i++) {
                int mrow = wm + i * 16 + g;
                unsigned a0 = f2tf32(As[cb][mrow][ks + t]);
                unsigned a1 = f2tf32(As[cb][mrow + 8][ks + t]);
                unsigned a2 = f2tf32(As[cb][mrow][ks + t + 4]);
                unsigned a3 = f2tf32(As[cb][mrow + 8][ks + t + 4]);
#pragma unroll
                for (int j = 0; j < 4; j++)
                    mma_tf32(acc[i][j], a0, a1, a2, a3, bfr[j][0], bfr[j][1]);
            }
        }
        __syncthreads();
    }
    (void)arow;
    (void)ak4;
#pragma unroll
    for (int i = 0; i < 4; i++) {
        int row = bm + wm + i * 16 + g;
#pragma unroll
        for (int j = 0; j < 4; j++) {
            int col = bn + wn + j * 8 + t * 2;
            *(float2*)&C[(size_t)row * N + col] = make_float2(acc[i][j][0], acc[i][j][1]);
            *(float2*)&C[(size_t)(row + 8) * N + col] = make_float2(acc[i][j][2], acc[i][j][3]);
        }
    }
}

// ---------------- reduces ----------------
__global__ void k_h2reduce() {
    int i = blockIdx.x * blockDim.x + threadIdx.x;
    if (i >= NN * HC2) return;
    g_h2[i] = g_gp2[i] + g_gp2[NN * HC2 + i];
}
__global__ void k_fcreduce(const float* __restrict__ bias) {
    int i = blockIdx.x * blockDim.x + threadIdx.x;
    if (i >= 512 * 512) return;
    float s = bias[i & 511];
#pragma unroll
    for (int p = 0; p < FC1_SPLITS; p++) s += g_fcp[p * 512 * 512 + i];
    g_fc1[i] = s > 0.f ? s : 0.f;
}

// ---------------- small GEMM with bias(+relu) (fc2) ---------------
template <bool RELU>
__global__ __launch_bounds__(256) void k_gemm64(int Atag, const float* __restrict__ B,
                                                const float* __restrict__ bias, int Ctag,
                                                int M, int N, int K) {
    const float* A = bufptr(Atag);
    float* C = bufptr(Ctag);
    __shared__ float As[16][64];
    __shared__ float Bs[16][64];
    int tid = threadIdx.x;
    int tx = tid & 15, ty = tid >> 4;
    int bm = blockIdx.y * 64, bn = blockIdx.x * 64;
    float acc[4][4];
#pragma unroll
    for (int r = 0; r < 4; r++)
#pragma unroll
        for (int c = 0; c < 4; c++) acc[r][c] = 0.f;

    for (int kt = 0; kt < K; kt += 16) {
        {
            int arow = tid >> 2, ak4 = tid & 3;
            float4 va = *(const float4*)&A[(size_t)(bm + arow) * K + kt + ak4 * 4];
            As[ak4 * 4 + 0][arow] = va.x;
            As[ak4 * 4 + 1][arow] = va.y;
            As[ak4 * 4 + 2][arow] = va.z;
            As[ak4 * 4 + 3][arow] = va.w;
            int brow = tid >> 4, bc4 = tid & 15;
            float4 vb = *(const float4*)&B[(size_t)(kt + brow) * N + bn + bc4 * 4];
            *(float4*)&Bs[brow][bc4 * 4] = vb;
        }
        __syncthreads();
#pragma unroll
        for (int kk = 0; kk < 16; kk++) {
            float a[4], b[4];
            *(float4*)a = *(const float4*)&As[kk][ty * 4];
            *(float4*)b = *(const float4*)&Bs[kk][tx * 4];
#pragma unroll
            for (int r = 0; r < 4; r++)
#pragma unroll
                for (int c = 0; c < 4; c++) acc[r][c] += a[r] * b[c];
        }
        __syncthreads();
    }
#pragma unroll
    for (int r = 0; r < 4; r++) {
        int m = bm + ty * 4 + r;
#pragma unroll
        for (int c = 0; c < 4; c++) {
            int n = bn + tx * 4 + c;
            float v = acc[r][c] + bias[n];
            if (RELU) v = v > 0.f ? v : 0.f;
            C[(size_t)m * N + n] = v;
        }
    }
}

// ---------------- per-(node,head) attention dots ----------------
__global__ void k_alpha(int htag, const float* __restrict__ a_s,
                        const float* __restrict__ a_d, int H, int C) {
    const float* h = bufptr(htag);
    int gw = (blockIdx.x * blockDim.x + threadIdx.x) >> 5;
    int lane = threadIdx.x & 31;
    if (gw >= NN * H) return;
    int n = gw / H, hd = gw - n * H;
    const float* hr = h + (size_t)n * H * C + (size_t)hd * C;
    const float* ws = a_s + hd * C;
    const float* wd = a_d + hd * C;
    float s1 = 0.f, s2 = 0.f;
    for (int c = lane; c < C; c += 32) {
        float v = hr[c];
        s1 += v * ws[c];
        s2 += v * wd[c];
    }
#pragma unroll
    for (int o = 16; o; o >>= 1) {
        s1 += __shfl_down_sync(0xffffffffu, s1, o);
        s2 += __shfl_down_sync(0xffffffffu, s2, o);
    }
    if (lane == 0) {
        g_as[gw] = s1;
        g_ad[gw] = s2;
    }
}

__global__ void k_edge(int H) {
    int i = blockIdx.x * blockDim.x + threadIdx.x;
    if (i >= ET * H) return;
    int e = i / H, hd = i - e * H;
    int src = g_srcv[e], dst = g_dstv[e];
    float v = g_as[src * H + hd] + g_ad[dst * H + hd];
    v = v > 0.f ? v : 0.2f * v;
    g_elog[i] = v;
    atomicMax(&g_m[dst * H + hd], f2u(v));
}

__global__ void k_exp(int H) {
    int i = blockIdx.x * blockDim.x + threadIdx.x;
    if (i >= ET * H) return;
    int e = i / H, hd = i - e * H;
    int dst = g_dstv[e];
    g_eexp[i] = expf(g_elog[i] - u2f(g_m[dst * H + hd]));
}

template <int PER, int H>
__global__ __launch_bounds__(256) void k_agg(int htag, const float* __restrict__ bias,
                                             int outtag) {
    const float* h = bufptr(htag);
    float* out = bufptr(outtag);
    const int HC = PER * 256;
    int n = blockIdx.x;
    int tid = threadIdx.x;
    int beg = g_rowptr[n], end = g_rowptr[n + 1];

    __shared__ float s_inv[H];
    if (tid < H) {
        float s = 0.f;
        for (int idx = beg; idx < end; ++idx) {
            int eid = g_eids[idx];
            s += g_eexp[eid * H + tid];
        }
        s_inv[tid] = 1.f / s;
    }
    __syncthreads();

    float acc[PER];
#pragma unroll
    for (int j = 0; j < PER; j++) acc[j] = 0.f;

    for (int idx = beg; idx < end; ++idx) {
        int eid = g_eids[idx];
        int src = g_srcv[eid];
        const float* hr = h + (size_t)src * HC;
        float aH[H];
#pragma unroll
        for (int hd = 0; hd < H; hd++) aH[hd] = g_eexp[eid * H + hd] * s_inv[hd];
#pragma unroll
        for (int j = 0; j < PER; j++) acc[j] += aH[j >> 1] * hr[tid + j * 256];
    }
#pragma unroll
    for (int j = 0; j < PER; j++) {
        int c = tid + j * 256;
        float v = acc[j] + bias[c];
        out[(size_t)n * HC + c] = v > 0.f ? v : 0.f;
    }
}

__global__ void k_fc3(int Atag, const float* __restrict__ W,
                      const float* __restrict__ b, float* __restrict__ out) {
    const float* A = bufptr(Atag);
    int i = blockIdx.x * blockDim.x + threadIdx.x;
    if (i >= 512 * 10) return;
    int m = i / 10, n = i - m * 10;
    float s = b[n];
#pragma unroll 8
    for (int k = 0; k < 128; k++) s += A[m * 128 + k] * W[k * 10 + n];
    out[i] = s;
}

extern "C" void kernel_launch(void* const* d_in, const int* in_sizes, int n_in,
                              void* d_out, int out_size) {
    const float* x = (const float*)d_in[0];
    const int* ei_raw = (const int*)d_in[1];
    const float* W1 = (const float*)d_in[3];
    const float* as1 = (const float*)d_in[4];
    const float* ad1 = (const float*)d_in[5];
    const float* b1 = (const float*)d_in[6];
    const float* W2 = (const float*)d_in[7];
    const float* as2 = (const float*)d_in[8];
    const float* ad2 = (const float*)d_in[9];
    const float* b2 = (const float*)d_in[10];
    const float* fc1w = (const float*)d_in[11];
    const float* fc1b = (const float*)d_in[12];
    const float* fc2w = (const float*)d_in[13];
    const float* fc2b = (const float*)d_in[14];
    const float* fc3w = (const float*)d_in[15];
    const float* fc3b = (const float*)d_in[16];
    float* out = (float*)d_out;

    // ---- normalize edge list + CSR build ----
    k_detect<<<1, 1024>>>(ei_raw);
    k_convert<<<(ET + 255) / 256, 256>>>(ei_raw);
    k_zero_csr<<<(NN + 255) / 256, 256>>>();
    k_hist<<<(ET + 255) / 256, 256>>>();
    k_scan<<<1, 1024>>>();
    k_scatter<<<(ET + 255) / 256, 256>>>();

    // ---- layer 1 ----
    k_mm_tf32<<<dim3(HC1 / 128, NN / 128, 1), 256>>>(x, -1, W1, B_H1, NN, HC1, 128, 128);
    k_alpha<<<(NN * HEADS1 * 32) / 256, 256>>>(B_H1, as1, ad1, HEADS1, 512);
    k_zero_m<<<(NN * HEADS1 + 255) / 256, 256>>>();
    k_edge<<<(ET * HEADS1 + 255) / 256, 256>>>(HEADS1);
    k_exp<<<(ET * HEADS1 + 255) / 256, 256>>>(HEADS1);
    k_agg<16, 8><<<NN, 256>>>(B_H1, b1, B_O1);

    // ---- layer 2: split-K=2 over K=4096 ----
    k_mm_tf32<<<dim3(HC2 / 128, NN / 128, 2), 256>>>(nullptr, B_O1, W2, B_GP2, NN, HC2,
                                                     HC1 / 2, HC1);
    k_h2reduce<<<(NN * HC2 + 255) / 256, 256>>>();
    k_alpha<<<(NN * 32 + 255) / 256, 256>>>(B_H2, as2, ad2, 1, 512);
    k_zero_m<<<(NN * HEADS1 + 255) / 256, 256>>>();
    k_edge<<<(ET + 255) / 256, 256>>>(1);
    k_exp<<<(ET + 255) / 256, 256>>>(1);
    k_agg<2, 1><<<NN, 256>>>(B_H2, b2, B_O2);

    // ---- MLP head ----
    k_mm_tf32<<<dim3(512 / 128, 512 / 128, FC1_SPLITS), 256>>>(
        nullptr, B_O2, fc1w, B_FCP, 512, 512, HC1 / FC1_SPLITS, HC1);
    k_fcreduce<<<(512 * 512 + 255) / 256, 256>>>(fc1b);
    k_gemm64<true><<<dim3(128 / 64, 512 / 64), 256>>>(B_FC1, fc2w, fc2b, B_FC2, 512, 128, 512);
    k_fc3<<<(512 * 10 + 255) / 256, 256>>>(B_FC2, fc3w, fc3b, out);
}

// round 9
// speedup vs baseline: 2.8651x; 1.0144x over previous
#include <cuda_runtime.h>
#include <math.h>

#define NN 4096
#define EE 32768
#define ET (EE + NN)
#define HEADS1 8
#define HC1 4096
#define HC2 512
#define FC1_SPLITS 8

// ---------------- scratch (device globals) ----------------
__device__ float g_h1[(size_t)NN * HC1];
__device__ float g_o1[(size_t)NN * HC1];
__device__ float g_h2[NN * HC2];
__device__ float g_o2[NN * HC2];
__device__ float g_as[NN * HEADS1];
__device__ float g_ad[NN * HEADS1];
__device__ float g_eexp[(size_t)ET * HEADS1];   // normalized alpha per (edge,head)
__device__ int g_rowptr[NN + 1];
__device__ int g_counts[NN];
__device__ int g_cursor[NN];
__device__ int g_eids[ET];
__device__ int g_srcv[ET];
__device__ int g_dstv[ET];
__device__ int g_flag64;
__device__ float g_fc1[512 * 512];
__device__ float g_fc2[512 * 128];
__device__ float g_fcp[FC1_SPLITS * 512 * 512];
__device__ float g_gp2[2 * NN * HC2];

#define B_H1 0
#define B_O1 1
#define B_H2 2
#define B_O2 3
#define B_FC1 4
#define B_FC2 5
#define B_FCP 6
#define B_GP2 7
__device__ __forceinline__ float* bufptr(int b) {
    switch (b) {
        case B_H1: return g_h1;
        case B_O1: return g_o1;
        case B_H2: return g_h2;
        case B_O2: return g_o2;
        case B_FC1: return g_fc1;
        case B_FC2: return g_fc2;
        case B_FCP: return g_fcp;
        default: return g_gp2;
    }
}

// ------------- tf32 + cp.async helpers -------------
__device__ __forceinline__ unsigned f2tf32(float f) {
    unsigned r;
    asm("cvt.rna.tf32.f32 %0, %1;" : "=r"(r) : "f"(f));
    return r;
}
__device__ __forceinline__ void mma_tf32(float* d, unsigned a0, unsigned a1, unsigned a2,
                                         unsigned a3, unsigned b0, unsigned b1) {
    asm volatile(
        "mma.sync.aligned.m16n8k8.row.col.f32.tf32.tf32.f32 "
        "{%0,%1,%2,%3}, {%4,%5,%6,%7}, {%8,%9}, {%0,%1,%2,%3};\n"
        : "+f"(d[0]), "+f"(d[1]), "+f"(d[2]), "+f"(d[3])
        : "r"(a0), "r"(a1), "r"(a2), "r"(a3), "r"(b0), "r"(b1));
}
__device__ __forceinline__ void cpasync16(void* s, const void* g) {
    unsigned sa = (unsigned)__cvta_generic_to_shared(s);
    asm volatile("cp.async.ca.shared.global [%0], [%1], 16;\n" ::"r"(sa), "l"(g));
}
__device__ __forceinline__ void cp_commit() { asm volatile("cp.async.commit_group;\n"); }
__device__ __forceinline__ void cp_wait1() { asm volatile("cp.async.wait_group 1;\n"); }
__device__ __forceinline__ void cp_wait0() { asm volatile("cp.async.wait_group 0;\n"); }

// ---------------- dtype probe + CSR zero (merged) ----------
__global__ void k_detect(const int* __restrict__ raw) {
    int t = threadIdx.x;
    for (int i = t; i < NN; i += 1024) {
        g_counts[i] = 0;
        g_cursor[i] = 0;
    }
    __shared__ int s_or;
    if (t == 0) s_or = 0;
    __syncthreads();
    int acc = 0;
    for (int i = t; i < 8192; i += 1024) acc |= raw[2 * i + 1];
    if (acc) atomicOr(&s_or, 1);
    __syncthreads();
    if (t == 0) g_flag64 = (s_or == 0) ? 1 : 0;
}

__global__ void k_convert(const int* __restrict__ raw) {
    int i = blockIdx.x * blockDim.x + threadIdx.x;
    if (i >= ET) return;
    if (i < EE) {
        if (g_flag64) {
            g_srcv[i] = raw[2 * i];
            g_dstv[i] = raw[2 * (EE + i)];
        } else {
            g_srcv[i] = raw[i];
            g_dstv[i] = raw[EE + i];
        }
    } else {
        g_srcv[i] = i - EE;
        g_dstv[i] = i - EE;
    }
}

__global__ void k_hist() {
    int i = blockIdx.x * blockDim.x + threadIdx.x;
    if (i >= ET) return;
    atomicAdd(&g_counts[g_dstv[i]], 1);
}

__global__ void k_scan() {
    __shared__ int s[1024];
    int t = threadIdx.x;
    int c0 = g_counts[4 * t + 0];
    int c1 = g_counts[4 * t + 1];
    int c2 = g_counts[4 * t + 2];
    int c3 = g_counts[4 * t + 3];
    int sum = c0 + c1 + c2 + c3;
    s[t] = sum;
    __syncthreads();
    for (int off = 1; off < 1024; off <<= 1) {
        int v = (t >= off) ? s[t - off] : 0;
        __syncthreads();
        s[t] += v;
        __syncthreads();
    }
    int excl = s[t] - sum;
    g_rowptr[4 * t + 0] = excl;
    g_rowptr[4 * t + 1] = excl + c0;
    g_rowptr[4 * t + 2] = excl + c0 + c1;
    g_rowptr[4 * t + 3] = excl + c0 + c1 + c2;
    if (t == 1023) g_rowptr[NN] = excl + sum;
}

__global__ void k_scatter() {
    int i = blockIdx.x * blockDim.x + threadIdx.x;
    if (i >= ET) return;
    int dst = g_dstv[i];
    int pos = g_rowptr[dst] + atomicAdd(&g_cursor[dst], 1);
    g_eids[pos] = i;
}

// ---------------- pipelined tf32 GEMM: 128x128 CTA tile, 4 warps @ 64x64 --------------
__global__ __launch_bounds__(128) void k_mm_tf32(const float* __restrict__ Aext, int Atag,
                                                 const float* __restrict__ Bsrc, int Ctag,
                                                 int M, int N, int Kc, int lda) {
    const float* A = Aext ? Aext : bufptr(Atag);
    float* C = bufptr(Ctag) + (size_t)blockIdx.z * M * N;
    int koff = blockIdx.z * Kc;
    __shared__ float As[2][128][20];   // m-major, stride 20 -> conflict-free frags
    __shared__ float Bs[2][16][136];   // k-major, stride 136 -> conflict-free frags
    int tid = threadIdx.x;
    int lane = tid & 31, wid = tid >> 5;
    int wm = (wid >> 1) * 64, wn = (wid & 1) * 64;
    int bm = blockIdx.y * 128, bn = blockIdx.x * 128;
    int g = lane >> 2, t = lane & 3;

    float acc[4][8][4];
#pragma unroll
    for (int i = 0; i < 4; i++)
#pragma unroll
        for (int j = 0; j < 8; j++)
#pragma unroll
            for (int r = 0; r < 4; r++) acc[i][j][r] = 0.f;

    const int NIT = Kc / 16;
#define LOAD_TILE(it, buf)                                                              \
    {                                                                                   \
        int kt = (it) * 16;                                                             \
        _Pragma("unroll") for (int i = 0; i < 4; i++) {                                 \
            int lid = tid + i * 128;                                                    \
            int ar = lid >> 2, a4 = lid & 3;                                            \
            cpasync16(&As[buf][ar][a4 * 4],                                             \
                      &A[(size_t)(bm + ar) * lda + koff + kt + a4 * 4]);                \
            int br = lid >> 5, b4 = lid & 31;                                           \
            cpasync16(&Bs[buf][br][b4 * 4],                                             \
                      &Bsrc[(size_t)(koff + kt + br) * N + bn + b4 * 4]);               \
        }                                                                               \
    }

    LOAD_TILE(0, 0);
    cp_commit();

    for (int it = 0; it < NIT; it++) {
        int cb = it & 1;
        if (it + 1 < NIT) {
            LOAD_TILE(it + 1, cb ^ 1);
            cp_commit();
            cp_wait1();
        } else {
            cp_wait0();
        }
        __syncthreads();
#pragma unroll
        for (int ks = 0; ks < 16; ks += 8) {
            unsigned bfr[8][2];
#pragma unroll
            for (int j = 0; j < 8; j++) {
                bfr[j][0] = f2tf32(Bs[cb][ks + t][wn + j * 8 + g]);
                bfr[j][1] = f2tf32(Bs[cb][ks + t + 4][wn + j * 8 + g]);
            }
#pragma unroll
            for (int i = 0; i < 4; i++) {
                int mrow = wm + i * 16 + g;
                unsigned a0 = f2tf32(As[cb][mrow][ks + t]);
                unsigned a1 = f2tf32(As[cb][mrow + 8][ks + t]);
                unsigned a2 = f2tf32(As[cb][mrow][ks + t + 4]);
                unsigned a3 = f2tf32(As[cb][mrow + 8][ks + t + 4]);
#pragma unroll
                for (int j = 0; j < 8; j++)
                    mma_tf32(acc[i][j], a0, a1, a2, a3, bfr[j][0], bfr[j][1]);
            }
        }
        __syncthreads();
    }
#pragma unroll
    for (int i = 0; i < 4; i++) {
        int row = bm + wm + i * 16 + g;
#pragma unroll
        for (int j = 0; j < 8; j++) {
            int col = bn + wn + j * 8 + t * 2;
            *(float2*)&C[(size_t)row * N + col] = make_float2(acc[i][j][0], acc[i][j][1]);
            *(float2*)&C[(size_t)(row + 8) * N + col] = make_float2(acc[i][j][2], acc[i][j][3]);
        }
    }
}

// ---------------- fc1 split-K reduce + bias + relu ----------------
__global__ void k_fcreduce(const float* __restrict__ bias) {
    int i = blockIdx.x * blockDim.x + threadIdx.x;
    if (i >= 512 * 512) return;
    float s = bias[i & 511];
#pragma unroll
    for (int p = 0; p < FC1_SPLITS; p++) s += g_fcp[p * 512 * 512 + i];
    g_fc1[i] = s > 0.f ? s : 0.f;
}

// ---------------- small GEMM with bias(+relu) (fc2) ---------------
template <bool RELU>
__global__ __launch_bounds__(256) void k_gemm64(int Atag, const float* __restrict__ B,
                                                const float* __restrict__ bias, int Ctag,
                                                int M, int N, int K) {
    const float* A = bufptr(Atag);
    float* C = bufptr(Ctag);
    __shared__ float As[16][64];
    __shared__ float Bs[16][64];
    int tid = threadIdx.x;
    int tx = tid & 15, ty = tid >> 4;
    int bm = blockIdx.y * 64, bn = blockIdx.x * 64;
    float acc[4][4];
#pragma unroll
    for (int r = 0; r < 4; r++)
#pragma unroll
        for (int c = 0; c < 4; c++) acc[r][c] = 0.f;

    for (int kt = 0; kt < K; kt += 16) {
        {
            int arow = tid >> 2, ak4 = tid & 3;
            float4 va = *(const float4*)&A[(size_t)(bm + arow) * K + kt + ak4 * 4];
            As[ak4 * 4 + 0][arow] = va.x;
            As[ak4 * 4 + 1][arow] = va.y;
            As[ak4 * 4 + 2][arow] = va.z;
            As[ak4 * 4 + 3][arow] = va.w;
            int brow = tid >> 4, bc4 = tid & 15;
            float4 vb = *(const float4*)&B[(size_t)(kt + brow) * N + bn + bc4 * 4];
            *(float4*)&Bs[brow][bc4 * 4] = vb;
        }
        __syncthreads();
#pragma unroll
        for (int kk = 0; kk < 16; kk++) {
            float a[4], b[4];
            *(float4*)a = *(const float4*)&As[kk][ty * 4];
            *(float4*)b = *(const float4*)&Bs[kk][tx * 4];
#pragma unroll
            for (int r = 0; r < 4; r++)
#pragma unroll
                for (int c = 0; c < 4; c++) acc[r][c] += a[r] * b[c];
        }
        __syncthreads();
    }
#pragma unroll
    for (int r = 0; r < 4; r++) {
        int m = bm + ty * 4 + r;
#pragma unroll
        for (int c = 0; c < 4; c++) {
            int n = bn + tx * 4 + c;
            float v = acc[r][c] + bias[n];
            if (RELU) v = v > 0.f ? v : 0.f;
            C[(size_t)m * N + n] = v;
        }
    }
}

// ---------------- per-(node,head) attention dots (layer 1) ----------------
__global__ void k_alpha(int htag, const float* __restrict__ a_s,
                        const float* __restrict__ a_d, int H, int C) {
    const float* h = bufptr(htag);
    int gw = (blockIdx.x * blockDim.x + threadIdx.x) >> 5;
    int lane = threadIdx.x & 31;
    if (gw >= NN * H) return;
    int n = gw / H, hd = gw - n * H;
    const float* hr = h + (size_t)n * H * C + (size_t)hd * C;
    const float* ws = a_s + hd * C;
    const float* wd = a_d + hd * C;
    float s1 = 0.f, s2 = 0.f;
    for (int c = lane; c < C; c += 32) {
        float v = hr[c];
        s1 += v * ws[c];
        s2 += v * wd[c];
    }
#pragma unroll
    for (int o = 16; o; o >>= 1) {
        s1 += __shfl_down_sync(0xffffffffu, s1, o);
        s2 += __shfl_down_sync(0xffffffffu, s2, o);
    }
    if (lane == 0) {
        g_as[gw] = s1;
        g_ad[gw] = s2;
    }
}

// ---------------- layer-2: reduce split-K partials -> h2, + attention dots ------------
__global__ void k_alpha2_red(const float* __restrict__ a_s, const float* __restrict__ a_d) {
    int gw = (blockIdx.x * blockDim.x + threadIdx.x) >> 5;
    int lane = threadIdx.x & 31;
    if (gw >= NN) return;
    const float* p0 = g_gp2 + (size_t)gw * HC2;
    const float* p1 = g_gp2 + (size_t)NN * HC2 + (size_t)gw * HC2;
    float* hr = g_h2 + (size_t)gw * HC2;
    float s1 = 0.f, s2 = 0.f;
    for (int c = lane; c < HC2; c += 32) {
        float v = p0[c] + p1[c];
        hr[c] = v;
        s1 += v * a_s[c];
        s2 += v * a_d[c];
    }
#pragma unroll
    for (int o = 16; o; o >>= 1) {
        s1 += __shfl_down_sync(0xffffffffu, s1, o);
        s2 += __shfl_down_sync(0xffffffffu, s2, o);
    }
    if (lane == 0) {
        g_as[gw] = s1;
        g_ad[gw] = s2;
    }
}

// ---------------- fused CSR edge softmax: one warp per (dst,head) --------------------
// writes NORMALIZED alpha into g_eexp[eid*H+hd]
template <int H, int NPB>
__global__ void k_softmax() {
    int wid = threadIdx.x >> 5, lane = threadIdx.x & 31;
    int n = blockIdx.x * NPB + wid / H;
    int hd = wid % H;
    int beg = g_rowptr[n], end = g_rowptr[n + 1];
    float adv = g_ad[n * H + hd];

    float mx = -1e30f;
    for (int i = beg + lane; i < end; i += 32) {
        int eid = g_eids[i];
        float v = g_as[g_srcv[eid] * H + hd] + adv;
        v = v > 0.f ? v : 0.2f * v;
        mx = fmaxf(mx, v);
    }
#pragma unroll
    for (int o = 16; o; o >>= 1) mx = fmaxf(mx, __shfl_xor_sync(0xffffffffu, mx, o));

    float s = 0.f;
    for (int i = beg + lane; i < end; i += 32) {
        int eid = g_eids[i];
        float v = g_as[g_srcv[eid] * H + hd] + adv;
        v = v > 0.f ? v : 0.2f * v;
        float e = expf(v - mx);
        g_eexp[eid * H + hd] = e;
        s += e;
    }
#pragma unroll
    for (int o = 16; o; o >>= 1) s += __shfl_xor_sync(0xffffffffu, s, o);
    float inv = 1.f / s;

    for (int i = beg + lane; i < end; i += 32) {
        int eid = g_eids[i];
        g_eexp[eid * H + hd] *= inv;
    }
}

// ---------------- CSR aggregate with prenormalized alpha ----------------
template <int PER, int H>
__global__ __launch_bounds__(256) void k_agg(int htag, const float* __restrict__ bias,
                                             int outtag) {
    const float* h = bufptr(htag);
    float* out = bufptr(outtag);
    const int HC = PER * 256;
    int n = blockIdx.x;
    int tid = threadIdx.x;
    int beg = g_rowptr[n], end = g_rowptr[n + 1];

    float acc[PER];
#pragma unroll
    for (int j = 0; j < PER; j++) acc[j] = 0.f;

    for (int idx = beg; idx < end; ++idx) {
        int eid = g_eids[idx];
        int src = g_srcv[eid];
        const float* hr = h + (size_t)src * HC;
        float aH[H];
#pragma unroll
        for (int hd = 0; hd < H; hd++) aH[hd] = g_eexp[eid * H + hd];
#pragma unroll
        for (int j = 0; j < PER; j++) acc[j] += aH[j >> 1] * hr[tid + j * 256];
    }
#pragma unroll
    for (int j = 0; j < PER; j++) {
        int c = tid + j * 256;
        float v = acc[j] + bias[c];
        out[(size_t)n * HC + c] = v > 0.f ? v : 0.f;
    }
}

// ---------------- fc3 ----------------
__global__ void k_fc3(int Atag, const float* __restrict__ W,
                      const float* __restrict__ b, float* __restrict__ out) {
    const float* A = bufptr(Atag);
    int i = blockIdx.x * blockDim.x + threadIdx.x;
    if (i >= 512 * 10) return;
    int m = i / 10, n = i - m * 10;
    float s = b[n];
#pragma unroll 8
    for (int k = 0; k < 128; k++) s += A[m * 128 + k] * W[k * 10 + n];
    out[i] = s;
}

extern "C" void kernel_launch(void* const* d_in, const int* in_sizes, int n_in,
                              void* d_out, int out_size) {
    const float* x = (const float*)d_in[0];
    const int* ei_raw = (const int*)d_in[1];
    const float* W1 = (const float*)d_in[3];
    const float* as1 = (const float*)d_in[4];
    const float* ad1 = (const float*)d_in[5];
    const float* b1 = (const float*)d_in[6];
    const float* W2 = (const float*)d_in[7];
    const float* as2 = (const float*)d_in[8];
    const float* ad2 = (const float*)d_in[9];
    const float* b2 = (const float*)d_in[10];
    const float* fc1w = (const float*)d_in[11];
    const float* fc1b = (const float*)d_in[12];
    const float* fc2w = (const float*)d_in[13];
    const float* fc2b = (const float*)d_in[14];
    const float* fc3w = (const float*)d_in[15];
    const float* fc3b = (const float*)d_in[16];
    float* out = (float*)d_out;

    // ---- normalize edge list + CSR build ----
    k_detect<<<1, 1024>>>(ei_raw);
    k_convert<<<(ET + 255) / 256, 256>>>(ei_raw);
    k_hist<<<(ET + 255) / 256, 256>>>();
    k_scan<<<1, 1024>>>();
    k_scatter<<<(ET + 255) / 256, 256>>>();

    // ---- layer 1 ----
    k_mm_tf32<<<dim3(HC1 / 128, NN / 128, 1), 128>>>(x, -1, W1, B_H1, NN, HC1, 128, 128);
    k_alpha<<<(NN * HEADS1 * 32) / 256, 256>>>(B_H1, as1, ad1, HEADS1, 512);
    k_softmax<HEADS1, 1><<<NN, 256>>>();
    k_agg<16, 8><<<NN, 256>>>(B_H1, b1, B_O1);

    // ---- layer 2: split-K=2 over K=4096 ----
    k_mm_tf32<<<dim3(HC2 / 128, NN / 128, 2), 128>>>(nullptr, B_O1, W2, B_GP2, NN, HC2,
                                                     HC1 / 2, HC1);
    k_alpha2_red<<<(NN * 32 + 255) / 256, 256>>>(as2, ad2);
    k_softmax<1, 8><<<NN / 8, 256>>>();
    k_agg<2, 1><<<NN, 256>>>(B_H2, b2, B_O2);

    // ---- MLP head ----
    k_mm_tf32<<<dim3(512 / 128, 512 / 128, FC1_SPLITS), 128>>>(
        nullptr, B_O2, fc1w, B_FCP, 512, 512, HC1 / FC1_SPLITS, HC1);
    k_fcreduce<<<(512 * 512 + 255) / 256, 256>>>(fc1b);
    k_gemm64<true><<<dim3(128 / 64, 512 / 64), 256>>>(B_FC1, fc2w, fc2b, B_FC2, 512, 128, 512);
    k_fc3<<<(512 * 10 + 255) / 256, 256>>>(B_FC2, fc3w, fc3b, out);
}

// round 11
// speedup vs baseline: 3.1968x; 1.1158x over previous
#include <cuda_runtime.h>
#include <math.h>

#define NN 4096
#define EE 32768
#define ET (EE + NN)
#define HEADS1 8
#define HC1 4096
#define HC2 512
#define FC1_SPLITS 8

// ---------------- scratch (device globals) ----------------
__device__ float g_h1[(size_t)NN * HC1];
__device__ float g_o1[(size_t)NN * HC1];
__device__ float g_h2[NN * HC2];
__device__ float g_o2[NN * HC2];
__device__ float g_as[NN * HEADS1];
__device__ float g_ad[NN * HEADS1];
__device__ float g_was[HEADS1 * 128];
__device__ float g_wad[HEADS1 * 128];
__device__ float g_eexp[(size_t)ET * HEADS1];
__device__ int g_rowptr[NN + 1];
__device__ int g_counts[NN];
__device__ int g_cursor[NN];
__device__ int g_eids[ET];
__device__ int g_srcv[ET];
__device__ int g_dstv[ET];
__device__ int g_flag64;
__device__ float g_fc1[512 * 512];
__device__ float g_fc2[512 * 128];
__device__ float g_fcp[FC1_SPLITS * 512 * 512];
__device__ float g_gp2[2 * NN * HC2];

#define B_H1 0
#define B_O1 1
#define B_H2 2
#define B_O2 3
#define B_FC1 4
#define B_FC2 5
#define B_FCP 6
#define B_GP2 7
__device__ __forceinline__ float* bufptr(int b) {
    switch (b) {
        case B_H1: return g_h1;
        case B_O1: return g_o1;
        case B_H2: return g_h2;
        case B_O2: return g_o2;
        case B_FC1: return g_fc1;
        case B_FC2: return g_fc2;
        case B_FCP: return g_fcp;
        default: return g_gp2;
    }
}

// ------------- fp16 pack + mma + cp.async helpers -------------
__device__ __forceinline__ unsigned f2h2(float lo, float hi) {
    unsigned d;
    asm("cvt.rn.f16x2.f32 %0, %1, %2;" : "=r"(d) : "f"(hi), "f"(lo));
    return d;
}
__device__ __forceinline__ void mma_f16(float* d, unsigned a0, unsigned a1, unsigned a2,
                                        unsigned a3, unsigned b0, unsigned b1) {
    asm volatile(
        "mma.sync.aligned.m16n8k16.row.col.f32.f16.f16.f32 "
        "{%0,%1,%2,%3}, {%4,%5,%6,%7}, {%8,%9}, {%0,%1,%2,%3};\n"
        : "+f"(d[0]), "+f"(d[1]), "+f"(d[2]), "+f"(d[3])
        : "r"(a0), "r"(a1), "r"(a2), "r"(a3), "r"(b0), "r"(b1));
}
__device__ __forceinline__ void cpasync16(void* s, const void* g) {
    unsigned sa = (unsigned)__cvta_generic_to_shared(s);
    asm volatile("cp.async.ca.shared.global [%0], [%1], 16;\n" ::"r"(sa), "l"(g));
}
__device__ __forceinline__ void cp_commit() { asm volatile("cp.async.commit_group;\n"); }
__device__ __forceinline__ void cp_wait1() { asm volatile("cp.async.wait_group 1;\n"); }
__device__ __forceinline__ void cp_wait0() { asm volatile("cp.async.wait_group 0;\n"); }

// ---------------- dtype probe + CSR zero ----------
__global__ void k_detect(const int* __restrict__ raw) {
    int t = threadIdx.x;
    for (int i = t; i < NN; i += 1024) {
        g_counts[i] = 0;
        g_cursor[i] = 0;
    }
    __shared__ int s_or;
    if (t == 0) s_or = 0;
    __syncthreads();
    int acc = 0;
    for (int i = t; i < 8192; i += 1024) acc |= raw[2 * i + 1];
    if (acc) atomicOr(&s_or, 1);
    __syncthreads();
    if (t == 0) g_flag64 = (s_or == 0) ? 1 : 0;
}

// convert + histogram (merged)
__global__ void k_convert(const int* __restrict__ raw) {
    int i = blockIdx.x * blockDim.x + threadIdx.x;
    if (i >= ET) return;
    int s, d;
    if (i < EE) {
        if (g_flag64) {
            s = raw[2 * i];
            d = raw[2 * (EE + i)];
        } else {
            s = raw[i];
            d = raw[EE + i];
        }
    } else {
        s = d = i - EE;
    }
    g_srcv[i] = s;
    g_dstv[i] = d;
    atomicAdd(&g_counts[d], 1);
}

__global__ void k_scan() {
    __shared__ int s[1024];
    int t = threadIdx.x;
    int c0 = g_counts[4 * t + 0];
    int c1 = g_counts[4 * t + 1];
    int c2 = g_counts[4 * t + 2];
    int c3 = g_counts[4 * t + 3];
    int sum = c0 + c1 + c2 + c3;
    s[t] = sum;
    __syncthreads();
    for (int off = 1; off < 1024; off <<= 1) {
        int v = (t >= off) ? s[t - off] : 0;
        __syncthreads();
        s[t] += v;
        __syncthreads();
    }
    int excl = s[t] - sum;
    g_rowptr[4 * t + 0] = excl;
    g_rowptr[4 * t + 1] = excl + c0;
    g_rowptr[4 * t + 2] = excl + c0 + c1;
    g_rowptr[4 * t + 3] = excl + c0 + c1 + c2;
    if (t == 1023) g_rowptr[NN] = excl + sum;
}

__global__ void k_scatter() {
    int i = blockIdx.x * blockDim.x + threadIdx.x;
    if (i >= ET) return;
    int dst = g_dstv[i];
    int pos = g_rowptr[dst] + atomicAdd(&g_cursor[dst], 1);
    g_eids[pos] = i;
}

// ---------------- fp16 tensor GEMM: 128x128 CTA tile, 4 warps @ 64x64, cp.async ------
__global__ __launch_bounds__(128) void k_mm(const float* __restrict__ Aext, int Atag,
                                            const float* __restrict__ Bsrc, int Ctag,
                                            int M, int N, int Kc, int lda) {
    const float* A = Aext ? Aext : bufptr(Atag);
    float* C = bufptr(Ctag) + (size_t)blockIdx.z * M * N;
    int koff = blockIdx.z * Kc;
    __shared__ float As[2][128][24];   // m-major, stride 24 -> conflict-free LDS.64
    __shared__ float Bs[2][16][136];   // k-major
    int tid = threadIdx.x;
    int lane = tid & 31, wid = tid >> 5;
    int wm = (wid >> 1) * 64, wn = (wid & 1) * 64;
    int bm = blockIdx.y * 128, bn = blockIdx.x * 128;
    int g = lane >> 2, t = lane & 3;

    float acc[4][8][4];
#pragma unroll
    for (int i = 0; i < 4; i++)
#pragma unroll
        for (int j = 0; j < 8; j++)
#pragma unroll
            for (int r = 0; r < 4; r++) acc[i][j][r] = 0.f;

    const int NIT = Kc / 16;
#define LOAD_TILE(it, buf)                                                              \
    {                                                                                   \
        int kt = (it) * 16;                                                             \
        _Pragma("unroll") for (int i = 0; i < 4; i++) {                                 \
            int lid = tid + i * 128;                                                    \
            int ar = lid >> 2, a4 = lid & 3;                                            \
            cpasync16(&As[buf][ar][a4 * 4],                                             \
                      &A[(size_t)(bm + ar) * lda + koff + kt + a4 * 4]);                \
            int br = lid >> 5, b4 = lid & 31;                                           \
            cpasync16(&Bs[buf][br][b4 * 4],                                             \
                      &Bsrc[(size_t)(koff + kt + br) * N + bn + b4 * 4]);               \
        }                                                                               \
    }

    LOAD_TILE(0, 0);
    cp_commit();

    for (int it = 0; it < NIT; it++) {
        int cb = it & 1;
        if (it + 1 < NIT) {
            LOAD_TILE(it + 1, cb ^ 1);
            cp_commit();
            cp_wait1();
        } else {
            cp_wait0();
        }
        __syncthreads();
        {
            unsigned bfr[8][2];
#pragma unroll
            for (int j = 0; j < 8; j++) {
                int n = wn + j * 8 + g;
                bfr[j][0] = f2h2(Bs[cb][2 * t][n], Bs[cb][2 * t + 1][n]);
                bfr[j][1] = f2h2(Bs[cb][2 * t + 8][n], Bs[cb][2 * t + 9][n]);
            }
#pragma unroll
            for (int i = 0; i < 4; i++) {
                int mrow = wm + i * 16 + g;
                float2 v0 = *(const float2*)&As[cb][mrow][2 * t];
                float2 v1 = *(const float2*)&As[cb][mrow + 8][2 * t];
                float2 v2 = *(const float2*)&As[cb][mrow][2 * t + 8];
                float2 v3 = *(const float2*)&As[cb][mrow + 8][2 * t + 8];
                unsigned a0 = f2h2(v0.x, v0.y);
                unsigned a1 = f2h2(v1.x, v1.y);
                unsigned a2 = f2h2(v2.x, v2.y);
                unsigned a3 = f2h2(v3.x, v3.y);
#pragma unroll
                for (int j = 0; j < 8; j++)
                    mma_f16(acc[i][j], a0, a1, a2, a3, bfr[j][0], bfr[j][1]);
            }
        }
        __syncthreads();
    }
#pragma unroll
    for (int i = 0; i < 4; i++) {
        int row = bm + wm + i * 16 + g;
#pragma unroll
        for (int j = 0; j < 8; j++) {
            int col = bn + wn + j * 8 + t * 2;
            *(float2*)&C[(size_t)row * N + col] = make_float2(acc[i][j][0], acc[i][j][1]);
            *(float2*)&C[(size_t)(row + 8) * N + col] = make_float2(acc[i][j][2], acc[i][j][3]);
        }
    }
}

// ---------------- fc1 split-K reduce + bias + relu ----------------
__global__ void k_fcreduce(const float* __restrict__ bias) {
    int i = blockIdx.x * blockDim.x + threadIdx.x;
    if (i >= 512 * 512) return;
    float s = bias[i & 511];
#pragma unroll
    for (int p = 0; p < FC1_SPLITS; p++) s += g_fcp[p * 512 * 512 + i];
    g_fc1[i] = s > 0.f ? s : 0.f;
}

// ---------------- small GEMM with bias(+relu) (fc2) ---------------
template <bool RELU>
__global__ __launch_bounds__(256) void k_gemm64(int Atag, const float* __restrict__ B,
                                                const float* __restrict__ bias, int Ctag,
                                                int M, int N, int K) {
    const float* A = bufptr(Atag);
    float* C = bufptr(Ctag);
    __shared__ float As[16][64];
    __shared__ float Bs[16][64];
    int tid = threadIdx.x;
    int tx = tid & 15, ty = tid >> 4;
    int bm = blockIdx.y * 64, bn = blockIdx.x * 64;
    float acc[4][4];
#pragma unroll
    for (int r = 0; r < 4; r++)
#pragma unroll
        for (int c = 0; c < 4; c++) acc[r][c] = 0.f;

    for (int kt = 0; kt < K; kt += 16) {
        {
            int arow = tid >> 2, ak4 = tid & 3;
            float4 va = *(const float4*)&A[(size_t)(bm + arow) * K + kt + ak4 * 4];
            As[ak4 * 4 + 0][arow] = va.x;
            As[ak4 * 4 + 1][arow] = va.y;
            As[ak4 * 4 + 2][arow] = va.z;
            As[ak4 * 4 + 3][arow] = va.w;
            int brow = tid >> 4, bc4 = tid & 15;
            float4 vb = *(const float4*)&B[(size_t)(kt + brow) * N + bn + bc4 * 4];
            *(float4*)&Bs[brow][bc4 * 4] = vb;
        }
        __syncthreads();
#pragma unroll
        for (int kk = 0; kk < 16; kk++) {
            float a[4], b[4];
            *(float4*)a = *(const float4*)&As[kk][ty * 4];
            *(float4*)b = *(const float4*)&Bs[kk][tx * 4];
#pragma unroll
            for (int r = 0; r < 4; r++)
#pragma unroll
                for (int c = 0; c < 4; c++) acc[r][c] += a[r] * b[c];
        }
        __syncthreads();
    }
#pragma unroll
    for (int r = 0; r < 4; r++) {
        int m = bm + ty * 4 + r;
#pragma unroll
        for (int c = 0; c < 4; c++) {
            int n = bn + tx * 4 + c;
            float v = acc[r][c] + bias[n];
            if (RELU) v = v > 0.f ? v : 0.f;
            C[(size_t)m * N + n] = v;
        }
    }
}

// ---------------- layer-1 alpha precompute: wa[h][k] = sum_c W1[k][h*512+c]*a[h][c] ----
__global__ void k_wa(const float* __restrict__ W1, const float* __restrict__ as1,
                     const float* __restrict__ ad1) {
    int w = (blockIdx.x * blockDim.x + threadIdx.x) >> 5;
    int lane = threadIdx.x & 31;
    if (w >= HEADS1 * 128) return;
    int h = w >> 7, k = w & 127;
    const float* wr = W1 + (size_t)k * HC1 + h * 512;
    const float* sp = as1 + h * 512;
    const float* dp = ad1 + h * 512;
    float s1 = 0.f, s2 = 0.f;
    for (int c = lane; c < 512; c += 32) {
        float wv = wr[c];
        s1 += wv * sp[c];
        s2 += wv * dp[c];
    }
#pragma unroll
    for (int o = 16; o; o >>= 1) {
        s1 += __shfl_down_sync(0xffffffffu, s1, o);
        s2 += __shfl_down_sync(0xffffffffu, s2, o);
    }
    if (lane == 0) {
        g_was[h * 128 + k] = s1;
        g_wad[h * 128 + k] = s2;
    }
}

// ---------------- layer-1 alpha: alpha[n][h] = x[n]·wa[h] ----------------
__global__ void k_alphax(const float* __restrict__ x) {
    int gw = (blockIdx.x * blockDim.x + threadIdx.x) >> 5;
    int lane = threadIdx.x & 31;
    if (gw >= NN * HEADS1) return;
    int n = gw >> 3, h = gw & 7;
    const float* xr = x + (size_t)n * 128;
    const float* ws = g_was + h * 128;
    const float* wd = g_wad + h * 128;
    float s1 = 0.f, s2 = 0.f;
#pragma unroll
    for (int i = 0; i < 4; i++) {
        int k = lane + i * 32;
        float v = xr[k];
        s1 += v * ws[k];
        s2 += v * wd[k];
    }
#pragma unroll
    for (int o = 16; o; o >>= 1) {
        s1 += __shfl_down_sync(0xffffffffu, s1, o);
        s2 += __shfl_down_sync(0xffffffffu, s2, o);
    }
    if (lane == 0) {
        g_as[gw] = s1;
        g_ad[gw] = s2;
    }
}

// ---------------- layer-2: reduce split-K partials -> h2, + attention dots ------------
__global__ void k_alpha2_red(const float* __restrict__ a_s, const float* __restrict__ a_d) {
    int gw = (blockIdx.x * blockDim.x + threadIdx.x) >> 5;
    int lane = threadIdx.x & 31;
    if (gw >= NN) return;
    const float* p0 = g_gp2 + (size_t)gw * HC2;
    const float* p1 = g_gp2 + (size_t)NN * HC2 + (size_t)gw * HC2;
    float* hr = g_h2 + (size_t)gw * HC2;
    float s1 = 0.f, s2 = 0.f;
    for (int c = lane; c < HC2; c += 32) {
        float v = p0[c] + p1[c];
        hr[c] = v;
        s1 += v * a_s[c];
        s2 += v * a_d[c];
    }
#pragma unroll
    for (int o = 16; o; o >>= 1) {
        s1 += __shfl_down_sync(0xffffffffu, s1, o);
        s2 += __shfl_down_sync(0xffffffffu, s2, o);
    }
    if (lane == 0) {
        g_as[gw] = s1;
        g_ad[gw] = s2;
    }
}

// ---------------- fused CSR edge softmax ----------------
template <int H, int NPB>
__global__ void k_softmax() {
    int wid = threadIdx.x >> 5, lane = threadIdx.x & 31;
    int n = blockIdx.x * NPB + wid / H;
    int hd = wid % H;
    int beg = g_rowptr[n], end = g_rowptr[n + 1];
    float adv = g_ad[n * H + hd];

    float mx = -1e30f;
    for (int i = beg + lane; i < end; i += 32) {
        int eid = g_eids[i];
        float v = g_as[g_srcv[eid] * H + hd] + adv;
        v = v > 0.f ? v : 0.2f * v;
        mx = fmaxf(mx, v);
    }
#pragma unroll
    for (int o = 16; o; o >>= 1) mx = fmaxf(mx, __shfl_xor_sync(0xffffffffu, mx, o));

    float s = 0.f;
    for (int i = beg + lane; i < end; i += 32) {
        int eid = g_eids[i];
        float v = g_as[g_srcv[eid] * H + hd] + adv;
        v = v > 0.f ? v : 0.2f * v;
        float e = expf(v - mx);
        g_eexp[eid * H + hd] = e;
        s += e;
    }
#pragma unroll
    for (int o = 16; o; o >>= 1) s += __shfl_xor_sync(0xffffffffu, s, o);
    float inv = 1.f / s;

    for (int i = beg + lane; i < end; i += 32) {
        int eid = g_eids[i];
        g_eexp[eid * H + hd] *= inv;
    }
}

// ---------------- CSR aggregate ----------------
template <int PER, int H>
__global__ __launch_bounds__(256) void k_agg(int htag, const float* __restrict__ bias,
                                             int outtag) {
    const float* h = bufptr(htag);
    float* out = bufptr(outtag);
    const int HC = PER * 256;
    int n = blockIdx.x;
    int tid = threadIdx.x;
    int beg = g_rowptr[n], end = g_rowptr[n + 1];

    float acc[PER];
#pragma unroll
    for (int j = 0; j < PER; j++) acc[j] = 0.f;

    for (int idx = beg; idx < end; ++idx) {
        int eid = g_eids[idx];
        int src = g_srcv[eid];
        const float* hr = h + (size_t)src * HC;
        float aH[H];
#pragma unroll
        for (int hd = 0; hd < H; hd++) aH[hd] = g_eexp[eid * H + hd];
#pragma unroll
        for (int j = 0; j < PER; j++) acc[j] += aH[j >> 1] * hr[tid + j * 256];
    }
#pragma unroll
    for (int j = 0; j < PER; j++) {
        int c = tid + j * 256;
        float v = acc[j] + bias[c];
        out[(size_t)n * HC + c] = v > 0.f ? v : 0.f;
    }
}

// ---------------- fc3 ----------------
__global__ void k_fc3(int Atag, const float* __restrict__ W,
                      const float* __restrict__ b, float* __restrict__ out) {
    const float* A = bufptr(Atag);
    int i = blockIdx.x * blockDim.x + threadIdx.x;
    if (i >= 512 * 10) return;
    int m = i / 10, n = i - m * 10;
    float s = b[n];
#pragma unroll 8
    for (int k = 0; k < 128; k++) s += A[m * 128 + k] * W[k * 10 + n];
    out[i] = s;
}

extern "C" void kernel_launch(void* const* d_in, const int* in_sizes, int n_in,
                              void* d_out, int out_size) {
    const float* x = (const float*)d_in[0];
    const int* ei_raw = (const int*)d_in[1];
    const float* W1 = (const float*)d_in[3];
    const float* as1 = (const float*)d_in[4];
    const float* ad1 = (const float*)d_in[5];
    const float* b1 = (const float*)d_in[6];
    const float* W2 = (const float*)d_in[7];
    const float* as2 = (const float*)d_in[8];
    const float* ad2 = (const float*)d_in[9];
    const float* b2 = (const float*)d_in[10];
    const float* fc1w = (const float*)d_in[11];
    const float* fc1b = (const float*)d_in[12];
    const float* fc2w = (const float*)d_in[13];
    const float* fc2b = (const float*)d_in[14];
    const float* fc3w = (const float*)d_in[15];
    const float* fc3b = (const float*)d_in[16];
    float* out = (float*)d_out;

    // ---- normalize edge list + CSR build ----
    k_detect<<<1, 1024>>>(ei_raw);
    k_convert<<<(ET + 255) / 256, 256>>>(ei_raw);
    k_scan<<<1, 1024>>>();
    k_scatter<<<(ET + 255) / 256, 256>>>();
    k_wa<<<(HEADS1 * 128) / 8, 256>>>(W1, as1, ad1);  // independent of GEMM

    // ---- layer 1 ----
    k_mm<<<dim3(HC1 / 128, NN / 128, 1), 128>>>(x, -1, W1, B_H1, NN, HC1, 128, 128);
    k_alphax<<<(NN * HEADS1) / 8, 256>>>(x);
    k_softmax<HEADS1, 1><<<NN, 256>>>();
    k_agg<16, 8><<<NN, 256>>>(B_H1, b1, B_O1);

    // ---- layer 2: split-K=2 over K=4096 ----
    k_mm<<<dim3(HC2 / 128, NN / 128, 2), 128>>>(nullptr, B_O1, W2, B_GP2, NN, HC2,
                                                HC1 / 2, HC1);
    k_alpha2_red<<<(NN * 32 + 255) / 256, 256>>>(as2, ad2);
    k_softmax<1, 8><<<NN / 8, 256>>>();
    k_agg<2, 1><<<NN, 256>>>(B_H2, b2, B_O2);

    // ---- MLP head ----
    k_mm<<<dim3(512 / 128, 512 / 128, FC1_SPLITS), 128>>>(
        nullptr, B_O2, fc1w, B_FCP, 512, 512, HC1 / FC1_SPLITS, HC1);
    k_fcreduce<<<(512 * 512 + 255) / 256, 256>>>(fc1b);
    k_gemm64<true><<<dim3(128 / 64, 512 / 64), 256>>>(B_FC1, fc2w, fc2b, B_FC2, 512, 128, 512);
    k_fc3<<<(512 * 10 + 255) / 256, 256>>>(B_FC2, fc3w, fc3b, out);
}

// round 12
// speedup vs baseline: 3.3713x; 1.0546x over previous
#include <cuda_runtime.h>
#include <cuda_fp16.h>
#include <math.h>

#define NN 4096
#define EE 32768
#define ET (EE + NN)
#define HEADS1 8
#define HC1 4096
#define HC2 512
#define FC1_SPLITS 8

// ---------------- scratch (device globals) ----------------
__device__ __half g_xh[NN * 128];
__device__ __half g_w1h[(size_t)HC1 * 128];      // W1^T fp16 [4096][128]
__device__ __half g_w2h[(size_t)HC2 * HC1];      // W2^T fp16 [512][4096]
__device__ __half g_fw1h[(size_t)512 * HC1];     // fc1w^T fp16 [512][4096]
__device__ __half g_h1h[(size_t)NN * HC1];
__device__ __half g_o1h[(size_t)NN * HC1];
__device__ __half g_h2h[NN * HC2];
__device__ __half g_o2h[NN * HC2];
__device__ float g_as[NN * HEADS1];
__device__ float g_ad[NN * HEADS1];
__device__ float g_was[HEADS1 * 128];
__device__ float g_wad[HEADS1 * 128];
__device__ float g_eexp[(size_t)ET * HEADS1];
__device__ int g_rowptr[NN + 1];
__device__ int g_counts[NN];
__device__ int g_cursor[NN];
__device__ int g_eids[ET];
__device__ int g_srcv[ET];
__device__ int g_dstv[ET];
__device__ int g_flag64;
__device__ float g_fc1[512 * 512];
__device__ float g_fc2[512 * 128];
__device__ float g_fcp[FC1_SPLITS * 512 * 512];
__device__ float g_gp2[2 * NN * HC2];

// float buffer tags
#define B_FC1 0
#define B_FC2 1
#define B_FCP 2
#define B_GP2 3
__device__ __forceinline__ float* bufptr(int b) {
    switch (b) {
        case B_FC1: return g_fc1;
        case B_FC2: return g_fc2;
        case B_FCP: return g_fcp;
        default: return g_gp2;
    }
}
// half buffer tags
#define H_XH 0
#define H_W1 1
#define H_W2 2
#define H_FW 3
#define H_H1 4
#define H_O1 5
#define H_H2 6
#define H_O2 7
__device__ __forceinline__ __half* hbuf(int b) {
    switch (b) {
        case H_XH: return g_xh;
        case H_W1: return g_w1h;
        case H_W2: return g_w2h;
        case H_FW: return g_fw1h;
        case H_H1: return g_h1h;
        case H_O1: return g_o1h;
        case H_H2: return g_h2h;
        default: return g_o2h;
    }
}

// ------------- mma + cp.async helpers -------------
__device__ __forceinline__ void mma_f16(float* d, unsigned a0, unsigned a1, unsigned a2,
                                        unsigned a3, unsigned b0, unsigned b1) {
    asm volatile(
        "mma.sync.aligned.m16n8k16.row.col.f32.f16.f16.f32 "
        "{%0,%1,%2,%3}, {%4,%5,%6,%7}, {%8,%9}, {%0,%1,%2,%3};\n"
        : "+f"(d[0]), "+f"(d[1]), "+f"(d[2]), "+f"(d[3])
        : "r"(a0), "r"(a1), "r"(a2), "r"(a3), "r"(b0), "r"(b1));
}
__device__ __forceinline__ void cpasync16(void* s, const void* g) {
    unsigned sa = (unsigned)__cvta_generic_to_shared(s);
    asm volatile("cp.async.ca.shared.global [%0], [%1], 16;\n" ::"r"(sa), "l"(g));
}
__device__ __forceinline__ void cp_commit() { asm volatile("cp.async.commit_group;\n"); }
__device__ __forceinline__ void cp_wait1() { asm volatile("cp.async.wait_group 1;\n"); }
__device__ __forceinline__ void cp_wait0() { asm volatile("cp.async.wait_group 0;\n"); }

// ---------------- dtype probe + CSR zero ----------
__global__ void k_detect(const int* __restrict__ raw) {
    int t = threadIdx.x;
    for (int i = t; i < NN; i += 1024) {
        g_counts[i] = 0;
        g_cursor[i] = 0;
    }
    __shared__ int s_or;
    if (t == 0) s_or = 0;
    __syncthreads();
    int acc = 0;
    for (int i = t; i < 8192; i += 1024) acc |= raw[2 * i + 1];
    if (acc) atomicOr(&s_or, 1);
    __syncthreads();
    if (t == 0) g_flag64 = (s_or == 0) ? 1 : 0;
}

__global__ void k_convert(const int* __restrict__ raw) {
    int i = blockIdx.x * blockDim.x + threadIdx.x;
    if (i >= ET) return;
    int s, d;
    if (i < EE) {
        if (g_flag64) {
            s = raw[2 * i];
            d = raw[2 * (EE + i)];
        } else {
            s = raw[i];
            d = raw[EE + i];
        }
    } else {
        s = d = i - EE;
    }
    g_srcv[i] = s;
    g_dstv[i] = d;
    atomicAdd(&g_counts[d], 1);
}

__global__ void k_scan() {
    __shared__ int s[1024];
    int t = threadIdx.x;
    int c0 = g_counts[4 * t + 0];
    int c1 = g_counts[4 * t + 1];
    int c2 = g_counts[4 * t + 2];
    int c3 = g_counts[4 * t + 3];
    int sum = c0 + c1 + c2 + c3;
    s[t] = sum;
    __syncthreads();
    for (int off = 1; off < 1024; off <<= 1) {
        int v = (t >= off) ? s[t - off] : 0;
        __syncthreads();
        s[t] += v;
        __syncthreads();
    }
    int excl = s[t] - sum;
    g_rowptr[4 * t + 0] = excl;
    g_rowptr[4 * t + 1] = excl + c0;
    g_rowptr[4 * t + 2] = excl + c0 + c1;
    g_rowptr[4 * t + 3] = excl + c0 + c1 + c2;
    if (t == 1023) g_rowptr[NN] = excl + sum;
}

__global__ void k_scatter() {
    int i = blockIdx.x * blockDim.x + threadIdx.x;
    if (i >= ET) return;
    int dst = g_dstv[i];
    int pos = g_rowptr[dst] + atomicAdd(&g_cursor[dst], 1);
    g_eids[pos] = i;
}

// ---------------- pre-converts ----------------
__global__ void k_cvt_x(const float* __restrict__ x) {
    int i = blockIdx.x * blockDim.x + threadIdx.x;
    if (i < NN * 128) g_xh[i] = __float2half(x[i]);
}
// transpose-convert: src fp32 [K][N] -> dst fp16 [N][K]
__global__ void k_cvtT(const float* __restrict__ src, int dtag, int K, int N) {
    __half* dst = hbuf(dtag);
    __shared__ float t[32][33];
    int kb = blockIdx.y * 32, nb = blockIdx.x * 32;
    int tx = threadIdx.x, ty = threadIdx.y;  // 32 x 8
    for (int r = ty; r < 32; r += 8) t[r][tx] = src[(size_t)(kb + r) * N + nb + tx];
    __syncthreads();
    for (int r = ty; r < 32; r += 8)
        dst[(size_t)(nb + r) * K + kb + tx] = __float2half(t[tx][r]);
}

// ---------------- fp16 GEMM: both operands k-major fp16, no in-loop cvt --------------
// C[M,N](+z*M*N) = A[M][lda] @ B[N][ldb]^T over columns koff..koff+Kc
template <bool OUTH>
__global__ __launch_bounds__(128) void k_mm_h(int Atag, int Btag, int Ctag,
                                              int M, int N, int Kc, int lda, int ldb) {
    const __half* Ag = hbuf(Atag);
    const __half* Bg = hbuf(Btag);
    int koff = blockIdx.z * Kc;
    __shared__ __half As[2][128][40];
    __shared__ __half Bs[2][128][40];
    int tid = threadIdx.x;
    int lane = tid & 31, wid = tid >> 5;
    int wm = (wid >> 1) * 64, wn = (wid & 1) * 64;
    int bm = blockIdx.y * 128, bn = blockIdx.x * 128;
    int g = lane >> 2, t = lane & 3;

    float acc[4][8][4];
#pragma unroll
    for (int i = 0; i < 4; i++)
#pragma unroll
        for (int j = 0; j < 8; j++)
#pragma unroll
            for (int r = 0; r < 4; r++) acc[i][j][r] = 0.f;

    const int NIT = Kc / 16;
#define LOADH(it, buf)                                                                   \
    {                                                                                    \
        int kt = koff + (it) * 16;                                                       \
        _Pragma("unroll") for (int i = 0; i < 2; i++) {                                  \
            int idx = tid + i * 128, r = idx >> 1, ch = idx & 1;                         \
            cpasync16(&As[buf][r][ch * 8], Ag + (size_t)(bm + r) * lda + kt + ch * 8);   \
        }                                                                                \
        _Pragma("unroll") for (int i = 0; i < 2; i++) {                                  \
            int idx = tid + i * 128, r = idx >> 1, ch = idx & 1;                         \
            cpasync16(&Bs[buf][r][ch * 8], Bg + (size_t)(bn + r) * ldb + kt + ch * 8);   \
        }                                                                                \
    }

    LOADH(0, 0);
    cp_commit();

    for (int it = 0; it < NIT; it++) {
        int cb = it & 1;
        if (it + 1 < NIT) {
            LOADH(it + 1, cb ^ 1);
            cp_commit();
            cp_wait1();
        } else {
            cp_wait0();
        }
        __syncthreads();
        {
            const unsigned* Ap = (const unsigned*)As[cb];
            const unsigned* Bp = (const unsigned*)Bs[cb];
            unsigned bfr[8][2];
#pragma unroll
            for (int j = 0; j < 8; j++) {
                int n = wn + j * 8 + g;
                bfr[j][0] = Bp[n * 20 + t];
                bfr[j][1] = Bp[n * 20 + t + 4];
            }
#pragma unroll
            for (int i = 0; i < 4; i++) {
                int mr = wm + i * 16 + g;
                unsigned a0 = Ap[mr * 20 + t];
                unsigned a1 = Ap[(mr + 8) * 20 + t];
                unsigned a2 = Ap[mr * 20 + t + 4];
                unsigned a3 = Ap[(mr + 8) * 20 + t + 4];
#pragma unroll
                for (int j = 0; j < 8; j++)
                    mma_f16(acc[i][j], a0, a1, a2, a3, bfr[j][0], bfr[j][1]);
            }
        }
        __syncthreads();
    }
    if (OUTH) {
        __half* Ch = hbuf(Ctag);
#pragma unroll
        for (int i = 0; i < 4; i++) {
            int row = bm + wm + i * 16 + g;
#pragma unroll
            for (int j = 0; j < 8; j++) {
                int col = bn + wn + j * 8 + t * 2;
                *(__half2*)&Ch[(size_t)row * N + col] =
                    __floats2half2_rn(acc[i][j][0], acc[i][j][1]);
                *(__half2*)&Ch[(size_t)(row + 8) * N + col] =
                    __floats2half2_rn(acc[i][j][2], acc[i][j][3]);
            }
        }
    } else {
        float* C = bufptr(Ctag) + (size_t)blockIdx.z * M * N;
#pragma unroll
        for (int i = 0; i < 4; i++) {
            int row = bm + wm + i * 16 + g;
#pragma unroll
            for (int j = 0; j < 8; j++) {
                int col = bn + wn + j * 8 + t * 2;
                *(float2*)&C[(size_t)row * N + col] = make_float2(acc[i][j][0], acc[i][j][1]);
                *(float2*)&C[(size_t)(row + 8) * N + col] =
                    make_float2(acc[i][j][2], acc[i][j][3]);
            }
        }
    }
}

// ---------------- fc1 split-K reduce + bias + relu ----------------
__global__ void k_fcreduce(const float* __restrict__ bias) {
    int i = blockIdx.x * blockDim.x + threadIdx.x;
    if (i >= 512 * 512) return;
    float s = bias[i & 511];
#pragma unroll
    for (int p = 0; p < FC1_SPLITS; p++) s += g_fcp[p * 512 * 512 + i];
    g_fc1[i] = s > 0.f ? s : 0.f;
}

// ---------------- small GEMM with bias(+relu) (fc2, fp32 SIMT) ---------------
template <bool RELU>
__global__ __launch_bounds__(256) void k_gemm64(int Atag, const float* __restrict__ B,
                                                const float* __restrict__ bias, int Ctag,
                                                int M, int N, int K) {
    const float* A = bufptr(Atag);
    float* C = bufptr(Ctag);
    __shared__ float As[16][64];
    __shared__ float Bs[16][64];
    int tid = threadIdx.x;
    int tx = tid & 15, ty = tid >> 4;
    int bm = blockIdx.y * 64, bn = blockIdx.x * 64;
    float acc[4][4];
#pragma unroll
    for (int r = 0; r < 4; r++)
#pragma unroll
        for (int c = 0; c < 4; c++) acc[r][c] = 0.f;

    for (int kt = 0; kt < K; kt += 16) {
        {
            int arow = tid >> 2, ak4 = tid & 3;
            float4 va = *(const float4*)&A[(size_t)(bm + arow) * K + kt + ak4 * 4];
            As[ak4 * 4 + 0][arow] = va.x;
            As[ak4 * 4 + 1][arow] = va.y;
            As[ak4 * 4 + 2][arow] = va.z;
            As[ak4 * 4 + 3][arow] = va.w;
            int brow = tid >> 4, bc4 = tid & 15;
            float4 vb = *(const float4*)&B[(size_t)(kt + brow) * N + bn + bc4 * 4];
            *(float4*)&Bs[brow][bc4 * 4] = vb;
        }
        __syncthreads();
#pragma unroll
        for (int kk = 0; kk < 16; kk++) {
            float a[4], b[4];
            *(float4*)a = *(const float4*)&As[kk][ty * 4];
            *(float4*)b = *(const float4*)&Bs[kk][tx * 4];
#pragma unroll
            for (int r = 0; r < 4; r++)
#pragma unroll
                for (int c = 0; c < 4; c++) acc[r][c] += a[r] * b[c];
        }
        __syncthreads();
    }
#pragma unroll
    for (int r = 0; r < 4; r++) {
        int m = bm + ty * 4 + r;
#pragma unroll
        for (int c = 0; c < 4; c++) {
            int n = bn + tx * 4 + c;
            float v = acc[r][c] + bias[n];
            if (RELU) v = v > 0.f ? v : 0.f;
            C[(size_t)m * N + n] = v;
        }
    }
}

// ---------------- layer-1 alpha precompute ----------------
__global__ void k_wa(const float* __restrict__ W1, const float* __restrict__ as1,
                     const float* __restrict__ ad1) {
    int w = (blockIdx.x * blockDim.x + threadIdx.x) >> 5;
    int lane = threadIdx.x & 31;
    if (w >= HEADS1 * 128) return;
    int h = w >> 7, k = w & 127;
    const float* wr = W1 + (size_t)k * HC1 + h * 512;
    const float* sp = as1 + h * 512;
    const float* dp = ad1 + h * 512;
    float s1 = 0.f, s2 = 0.f;
    for (int c = lane; c < 512; c += 32) {
        float wv = wr[c];
        s1 += wv * sp[c];
        s2 += wv * dp[c];
    }
#pragma unroll
    for (int o = 16; o; o >>= 1) {
        s1 += __shfl_down_sync(0xffffffffu, s1, o);
        s2 += __shfl_down_sync(0xffffffffu, s2, o);
    }
    if (lane == 0) {
        g_was[h * 128 + k] = s1;
        g_wad[h * 128 + k] = s2;
    }
}

__global__ void k_alphax(const float* __restrict__ x) {
    int gw = (blockIdx.x * blockDim.x + threadIdx.x) >> 5;
    int lane = threadIdx.x & 31;
    if (gw >= NN * HEADS1) return;
    int n = gw >> 3, h = gw & 7;
    const float* xr = x + (size_t)n * 128;
    const float* ws = g_was + h * 128;
    const float* wd = g_wad + h * 128;
    float s1 = 0.f, s2 = 0.f;
#pragma unroll
    for (int i = 0; i < 4; i++) {
        int k = lane + i * 32;
        float v = xr[k];
        s1 += v * ws[k];
        s2 += v * wd[k];
    }
#pragma unroll
    for (int o = 16; o; o >>= 1) {
        s1 += __shfl_down_sync(0xffffffffu, s1, o);
        s2 += __shfl_down_sync(0xffffffffu, s2, o);
    }
    if (lane == 0) {
        g_as[gw] = s1;
        g_ad[gw] = s2;
    }
}

// ---------------- layer-2: reduce split-K -> h2 fp16, + dots ------------
__global__ void k_alpha2_red(const float* __restrict__ a_s, const float* __restrict__ a_d) {
    int gw = (blockIdx.x * blockDim.x + threadIdx.x) >> 5;
    int lane = threadIdx.x & 31;
    if (gw >= NN) return;
    const float* p0 = g_gp2 + (size_t)gw * HC2;
    const float* p1 = g_gp2 + (size_t)NN * HC2 + (size_t)gw * HC2;
    __half* hr = g_h2h + (size_t)gw * HC2;
    float s1 = 0.f, s2 = 0.f;
    for (int c = lane; c < HC2; c += 32) {
        float v = p0[c] + p1[c];
        hr[c] = __float2half(v);
        s1 += v * a_s[c];
        s2 += v * a_d[c];
    }
#pragma unroll
    for (int o = 16; o; o >>= 1) {
        s1 += __shfl_down_sync(0xffffffffu, s1, o);
        s2 += __shfl_down_sync(0xffffffffu, s2, o);
    }
    if (lane == 0) {
        g_as[gw] = s1;
        g_ad[gw] = s2;
    }
}

// ---------------- fused CSR edge softmax ----------------
template <int H, int NPB>
__global__ void k_softmax() {
    int wid = threadIdx.x >> 5, lane = threadIdx.x & 31;
    int n = blockIdx.x * NPB + wid / H;
    int hd = wid % H;
    int beg = g_rowptr[n], end = g_rowptr[n + 1];
    float adv = g_ad[n * H + hd];

    float mx = -1e30f;
    for (int i = beg + lane; i < end; i += 32) {
        int eid = g_eids[i];
        float v = g_as[g_srcv[eid] * H + hd] + adv;
        v = v > 0.f ? v : 0.2f * v;
        mx = fmaxf(mx, v);
    }
#pragma unroll
    for (int o = 16; o; o >>= 1) mx = fmaxf(mx, __shfl_xor_sync(0xffffffffu, mx, o));

    float s = 0.f;
    for (int i = beg + lane; i < end; i += 32) {
        int eid = g_eids[i];
        float v = g_as[g_srcv[eid] * H + hd] + adv;
        v = v > 0.f ? v : 0.2f * v;
        float e = expf(v - mx);
        g_eexp[eid * H + hd] = e;
        s += e;
    }
#pragma unroll
    for (int o = 16; o; o >>= 1) s += __shfl_xor_sync(0xffffffffu, s, o);
    float inv = 1.f / s;

    for (int i = beg + lane; i < end; i += 32) {
        int eid = g_eids[i];
        g_eexp[eid * H + hd] *= inv;
    }
}

// ---------------- layer-1 CSR aggregate (fp16 h, fp16 out) ----------------
__global__ __launch_bounds__(256) void k_agg1(const float* __restrict__ bias) {
    int n = blockIdx.x, tid = threadIdx.x;
    int c0 = tid * 16, head = tid >> 5;
    int beg = g_rowptr[n], end = g_rowptr[n + 1];
    float acc[16];
#pragma unroll
    for (int j = 0; j < 16; j++) acc[j] = 0.f;

    for (int idx = beg; idx < end; ++idx) {
        int eid = g_eids[idx];
        int src = g_srcv[eid];
        float al = g_eexp[eid * 8 + head];
        const uint4* hp = (const uint4*)(g_h1h + (size_t)src * HC1 + c0);
        uint4 u0 = hp[0], u1 = hp[1];
        unsigned w[8] = {u0.x, u0.y, u0.z, u0.w, u1.x, u1.y, u1.z, u1.w};
#pragma unroll
        for (int j = 0; j < 8; j++) {
            float2 f = __half22float2(*(__half2*)&w[j]);
            acc[2 * j] += al * f.x;
            acc[2 * j + 1] += al * f.y;
        }
    }
    unsigned ow[8];
#pragma unroll
    for (int j = 0; j < 8; j++) {
        float v0 = acc[2 * j] + bias[c0 + 2 * j];
        float v1 = acc[2 * j + 1] + bias[c0 + 2 * j + 1];
        v0 = v0 > 0.f ? v0 : 0.f;
        v1 = v1 > 0.f ? v1 : 0.f;
        __half2 p = __floats2half2_rn(v0, v1);
        ow[j] = *(unsigned*)&p;
    }
    uint4* op = (uint4*)(g_o1h + (size_t)n * HC1 + c0);
    op[0] = make_uint4(ow[0], ow[1], ow[2], ow[3]);
    op[1] = make_uint4(ow[4], ow[5], ow[6], ow[7]);
}

// ---------------- layer-2 CSR aggregate (fp16 h, fp16 out) ----------------
__global__ __launch_bounds__(256) void k_agg2(const float* __restrict__ bias) {
    int n = blockIdx.x, tid = threadIdx.x;
    int c0 = tid * 2;
    int beg = g_rowptr[n], end = g_rowptr[n + 1];
    float a0 = 0.f, a1 = 0.f;
    for (int idx = beg; idx < end; ++idx) {
        int eid = g_eids[idx];
        int src = g_srcv[eid];
        float al = g_eexp[eid];
        float2 f = __half22float2(*(const __half2*)(g_h2h + (size_t)src * HC2 + c0));
        a0 += al * f.x;
        a1 += al * f.y;
    }
    float v0 = a0 + bias[c0], v1 = a1 + bias[c0 + 1];
    v0 = v0 > 0.f ? v0 : 0.f;
    v1 = v1 > 0.f ? v1 : 0.f;
    *(__half2*)(g_o2h + (size_t)n * HC2 + c0) = __floats2half2_rn(v0, v1);
}

// ---------------- fc3 ----------------
__global__ void k_fc3(int Atag, const float* __restrict__ W,
                      const float* __restrict__ b, float* __restrict__ out) {
    const float* A = bufptr(Atag);
    int i = blockIdx.x * blockDim.x + threadIdx.x;
    if (i >= 512 * 10) return;
    int m = i / 10, n = i - m * 10;
    float s = b[n];
#pragma unroll 8
    for (int k = 0; k < 128; k++) s += A[m * 128 + k] * W[k * 10 + n];
    out[i] = s;
}

extern "C" void kernel_launch(void* const* d_in, const int* in_sizes, int n_in,
                              void* d_out, int out_size) {
    const float* x = (const float*)d_in[0];
    const int* ei_raw = (const int*)d_in[1];
    const float* W1 = (const float*)d_in[3];
    const float* as1 = (const float*)d_in[4];
    const float* ad1 = (const float*)d_in[5];
    const float* b1 = (const float*)d_in[6];
    const float* W2 = (const float*)d_in[7];
    const float* as2 = (const float*)d_in[8];
    const float* ad2 = (const float*)d_in[9];
    const float* b2 = (const float*)d_in[10];
    const float* fc1w = (const float*)d_in[11];
    const float* fc1b = (const float*)d_in[12];
    const float* fc2w = (const float*)d_in[13];
    const float* fc2b = (const float*)d_in[14];
    const float* fc3w = (const float*)d_in[15];
    const float* fc3b = (const float*)d_in[16];
    float* out = (float*)d_out;

    dim3 tdim(32, 8);

    // ---- CSR build + pre-converts (independent work up front) ----
    k_detect<<<1, 1024>>>(ei_raw);
    k_cvt_x<<<(NN * 128 + 255) / 256, 256>>>(x);
    k_cvtT<<<dim3(HC1 / 32, 128 / 32), tdim>>>(W1, H_W1, 128, HC1);
    k_cvtT<<<dim3(HC2 / 32, HC1 / 32), tdim>>>(W2, H_W2, HC1, HC2);
    k_cvtT<<<dim3(512 / 32, HC1 / 32), tdim>>>(fc1w, H_FW, HC1, 512);
    k_wa<<<(HEADS1 * 128) / 8, 256>>>(W1, as1, ad1);
    k_convert<<<(ET + 255) / 256, 256>>>(ei_raw);
    k_scan<<<1, 1024>>>();
    k_scatter<<<(ET + 255) / 256, 256>>>();

    // ---- layer 1 ----
    k_mm_h<true><<<dim3(HC1 / 128, NN / 128, 1), 128>>>(H_XH, H_W1, H_H1, NN, HC1, 128,
                                                        128, 128);
    k_alphax<<<(NN * HEADS1) / 8, 256>>>(x);
    k_softmax<HEADS1, 1><<<NN, 256>>>();
    k_agg1<<<NN, 256>>>(b1);

    // ---- layer 2: split-K=2 ----
    k_mm_h<false><<<dim3(HC2 / 128, NN / 128, 2), 128>>>(H_O1, H_W2, B_GP2, NN, HC2,
                                                         HC1 / 2, HC1, HC1);
    k_alpha2_red<<<(NN * 32 + 255) / 256, 256>>>(as2, ad2);
    k_softmax<1, 8><<<NN / 8, 256>>>();
    k_agg2<<<NN, 256>>>(b2);

    // ---- MLP head ----
    k_mm_h<false><<<dim3(512 / 128, 512 / 128, FC1_SPLITS), 128>>>(
        H_O2, H_FW, B_FCP, 512, 512, HC1 / FC1_SPLITS, HC1, HC1);
    k_fcreduce<<<(512 * 512 + 255) / 256, 256>>>(fc1b);
    k_gemm64<true><<<dim3(128 / 64, 512 / 64), 256>>>(B_FC1, fc2w, fc2b, B_FC2, 512, 128, 512);
    k_fc3<<<(512 * 10 + 255) / 256, 256>>>(B_FC2, fc3w, fc3b, out);
}

// round 14
// speedup vs baseline: 3.8256x; 1.1348x over previous
#include <cuda_runtime.h>
#include <cuda_fp16.h>
#include <math.h>

#define NN 4096
#define EE 32768
#define ET (EE + NN)
#define HEADS1 8
#define HC1 4096
#define HC2 512
#define FC1_SPLITS 8

// ---------------- scratch (device globals) ----------------
__device__ __half g_xh[NN * 128];
__device__ __half g_w1h[(size_t)128 * HC1];      // W1 fp16 [128][4096] (k-major)
__device__ __half g_w2h[(size_t)HC1 * HC2];      // W2 fp16 [4096][512]
__device__ __half g_fw1h[(size_t)HC1 * 512];     // fc1w fp16 [4096][512]
__device__ __half g_h1h[(size_t)NN * HC1];
__device__ __half g_o1h[(size_t)NN * HC1];
__device__ __half g_h2h[NN * HC2];
__device__ __half g_o2h[NN * HC2];
__device__ float g_as[NN * HEADS1];
__device__ float g_ad[NN * HEADS1];
__device__ float g_was[HEADS1 * 128];
__device__ float g_wad[HEADS1 * 128];
__device__ float g_eexp[(size_t)ET * HEADS1];
__device__ int g_rowptr[NN + 1];
__device__ int g_counts[NN];
__device__ int g_cursor[NN];
__device__ int g_eids[ET];
__device__ int g_srcv[ET];
__device__ int g_dstv[ET];
__device__ int g_flag64;
__device__ float g_fc1[512 * 512];
__device__ float g_fc2[512 * 128];
__device__ float g_fcp[FC1_SPLITS * 512 * 512];
__device__ float g_gp2[2 * NN * HC2];

// float buffer tags
#define B_FC1 0
#define B_FC2 1
#define B_FCP 2
#define B_GP2 3
__device__ __forceinline__ float* bufptr(int b) {
    switch (b) {
        case B_FC1: return g_fc1;
        case B_FC2: return g_fc2;
        case B_FCP: return g_fcp;
        default: return g_gp2;
    }
}
// half buffer tags
#define H_XH 0
#define H_W1 1
#define H_W2 2
#define H_FW 3
#define H_H1 4
#define H_O1 5
#define H_H2 6
#define H_O2 7
__device__ __forceinline__ __half* hbuf(int b) {
    switch (b) {
        case H_XH: return g_xh;
        case H_W1: return g_w1h;
        case H_W2: return g_w2h;
        case H_FW: return g_fw1h;
        case H_H1: return g_h1h;
        case H_O1: return g_o1h;
        case H_H2: return g_h2h;
        default: return g_o2h;
    }
}

// ------------- mma + ldmatrix + cp.async helpers -------------
__device__ __forceinline__ void mma_f16(float* d, unsigned a0, unsigned a1, unsigned a2,
                                        unsigned a3, unsigned b0, unsigned b1) {
    asm volatile(
        "mma.sync.aligned.m16n8k16.row.col.f32.f16.f16.f32 "
        "{%0,%1,%2,%3}, {%4,%5,%6,%7}, {%8,%9}, {%0,%1,%2,%3};\n"
        : "+f"(d[0]), "+f"(d[1]), "+f"(d[2]), "+f"(d[3])
        : "r"(a0), "r"(a1), "r"(a2), "r"(a3), "r"(b0), "r"(b1));
}
__device__ __forceinline__ void ldsm4(unsigned* r, const void* p) {
    unsigned a = (unsigned)__cvta_generic_to_shared(p);
    asm volatile("ldmatrix.sync.aligned.m8n8.x4.shared.b16 {%0,%1,%2,%3}, [%4];"
                 : "=r"(r[0]), "=r"(r[1]), "=r"(r[2]), "=r"(r[3]) : "r"(a));
}
__device__ __forceinline__ void ldsm4t(unsigned* r, const void* p) {
    unsigned a = (unsigned)__cvta_generic_to_shared(p);
    asm volatile("ldmatrix.sync.aligned.m8n8.x4.trans.shared.b16 {%0,%1,%2,%3}, [%4];"
                 : "=r"(r[0]), "=r"(r[1]), "=r"(r[2]), "=r"(r[3]) : "r"(a));
}
__device__ __forceinline__ void cpasync16(void* s, const void* g) {
    unsigned sa = (unsigned)__cvta_generic_to_shared(s);
    asm volatile("cp.async.ca.shared.global [%0], [%1], 16;\n" ::"r"(sa), "l"(g));
}
__device__ __forceinline__ void cp_commit() { asm volatile("cp.async.commit_group;\n"); }
__device__ __forceinline__ void cp_wait1() { asm volatile("cp.async.wait_group 1;\n"); }
__device__ __forceinline__ void cp_wait0() { asm volatile("cp.async.wait_group 0;\n"); }

// ---------------- dtype probe + CSR zero ----------
__global__ void k_detect(const int* __restrict__ raw) {
    int t = threadIdx.x;
    for (int i = t; i < NN; i += 1024) {
        g_counts[i] = 0;
        g_cursor[i] = 0;
    }
    __shared__ int s_or;
    if (t == 0) s_or = 0;
    __syncthreads();
    int acc = 0;
    for (int i = t; i < 8192; i += 1024) acc |= raw[2 * i + 1];
    if (acc) atomicOr(&s_or, 1);
    __syncthreads();
    if (t == 0) g_flag64 = (s_or == 0) ? 1 : 0;
}

__global__ void k_convert(const int* __restrict__ raw) {
    int i = blockIdx.x * blockDim.x + threadIdx.x;
    if (i >= ET) return;
    int s, d;
    if (i < EE) {
        if (g_flag64) {
            s = raw[2 * i];
            d = raw[2 * (EE + i)];
        } else {
            s = raw[i];
            d = raw[EE + i];
        }
    } else {
        s = d = i - EE;
    }
    g_srcv[i] = s;
    g_dstv[i] = d;
    atomicAdd(&g_counts[d], 1);
}

__global__ void k_scan() {
    __shared__ int s[1024];
    int t = threadIdx.x;
    int c0 = g_counts[4 * t + 0];
    int c1 = g_counts[4 * t + 1];
    int c2 = g_counts[4 * t + 2];
    int c3 = g_counts[4 * t + 3];
    int sum = c0 + c1 + c2 + c3;
    s[t] = sum;
    __syncthreads();
    for (int off = 1; off < 1024; off <<= 1) {
        int v = (t >= off) ? s[t - off] : 0;
        __syncthreads();
        s[t] += v;
        __syncthreads();
    }
    int excl = s[t] - sum;
    g_rowptr[4 * t + 0] = excl;
    g_rowptr[4 * t + 1] = excl + c0;
    g_rowptr[4 * t + 2] = excl + c0 + c1;
    g_rowptr[4 * t + 3] = excl + c0 + c1 + c2;
    if (t == 1023) g_rowptr[NN] = excl + sum;
}

__global__ void k_scatter() {
    int i = blockIdx.x * blockDim.x + threadIdx.x;
    if (i >= ET) return;
    int dst = g_dstv[i];
    int pos = g_rowptr[dst] + atomicAdd(&g_cursor[dst], 1);
    g_eids[pos] = i;
}

// ---------------- straight fp32->fp16 convert (8 elems/thread) ----------------
__global__ void k_cvt(const float* __restrict__ src, int dtag, int n) {
    __half* dst = hbuf(dtag);
    int i = (blockIdx.x * blockDim.x + threadIdx.x) * 8;
    if (i >= n) return;
    float4 a = *(const float4*)&src[i];
    float4 b = *(const float4*)&src[i + 4];
    __half2 h0 = __floats2half2_rn(a.x, a.y);
    __half2 h1 = __floats2half2_rn(a.z, a.w);
    __half2 h2 = __floats2half2_rn(b.x, b.y);
    __half2 h3 = __floats2half2_rn(b.z, b.w);
    *(uint4*)&dst[i] = make_uint4(*(unsigned*)&h0, *(unsigned*)&h1, *(unsigned*)&h2,
                                  *(unsigned*)&h3);
}

// ---------------- fp16 GEMM: A m-major, B k-major, ldmatrix frags ----------------
// C[M,N](+z*M*N) = A[M][lda] @ B[K][ldbN] over rows koff..koff+Kc of B
template <bool OUTH>
__global__ __launch_bounds__(128) void k_mm_h(int Atag, int Btag, int Ctag,
                                              int M, int N, int Kc, int lda, int ldbN) {
    const __half* Ag = hbuf(Atag);
    const __half* Bg = hbuf(Btag);
    int koff = blockIdx.z * Kc;
    __shared__ __half As[2][128][24];   // [m][k] rows 48B: 16B-aligned + bank-spread
    __shared__ __half Bs[2][16][136];   // [k][n] rows 272B
    int tid = threadIdx.x;
    int lane = tid & 31, wid = tid >> 5;
    int wm = (wid >> 1) * 64, wn = (wid & 1) * 64;
    int bm = blockIdx.y * 128, bn = blockIdx.x * 128;
    int g = lane >> 2, t = lane & 3;

    float acc[4][8][4];
#pragma unroll
    for (int i = 0; i < 4; i++)
#pragma unroll
        for (int j = 0; j < 8; j++)
#pragma unroll
            for (int r = 0; r < 4; r++) acc[i][j][r] = 0.f;

    const int NIT = Kc / 16;
    int l16 = lane & 15, lhi = lane >> 4;
#define LOADH(it, buf)                                                                   \
    {                                                                                    \
        int kt = koff + (it) * 16;                                                       \
        _Pragma("unroll") for (int i = 0; i < 2; i++) {                                  \
            int idx = tid + i * 128, r = idx >> 1, ch = idx & 1;                         \
            cpasync16(&As[buf][r][ch * 8], Ag + (size_t)(bm + r) * lda + kt + ch * 8);   \
        }                                                                                \
        _Pragma("unroll") for (int i = 0; i < 2; i++) {                                  \
            int idx = tid + i * 128, r = idx >> 4, ch = idx & 15;                        \
            cpasync16(&Bs[buf][r][ch * 8], Bg + (size_t)(kt + r) * ldbN + bn + ch * 8);  \
        }                                                                                \
    }

    LOADH(0, 0);
    cp_commit();

    for (int it = 0; it < NIT; it++) {
        int cb = it & 1;
        if (it + 1 < NIT) {
            LOADH(it + 1, cb ^ 1);
            cp_commit();
            cp_wait1();
        } else {
            cp_wait0();
        }
        __syncthreads();
        {
            unsigned af[4][4], bf[4][4];
#pragma unroll
            for (int i = 0; i < 4; i++)
                ldsm4(af[i], &As[cb][wm + i * 16 + l16][lhi * 8]);
#pragma unroll
            for (int j4 = 0; j4 < 4; j4++)
                ldsm4t(bf[j4], &Bs[cb][l16][wn + j4 * 16 + lhi * 8]);
#pragma unroll
            for (int i = 0; i < 4; i++)
#pragma unroll
                for (int j4 = 0; j4 < 4; j4++) {
                    mma_f16(acc[i][2 * j4], af[i][0], af[i][1], af[i][2], af[i][3],
                            bf[j4][0], bf[j4][1]);
                    mma_f16(acc[i][2 * j4 + 1], af[i][0], af[i][1], af[i][2], af[i][3],
                            bf[j4][2], bf[j4][3]);
                }
        }
        __syncthreads();
    }
    if (OUTH) {
        __half* Ch = hbuf(Ctag);
#pragma unroll
        for (int i = 0; i < 4; i++) {
            int row = bm + wm + i * 16 + g;
#pragma unroll
            for (int j = 0; j < 8; j++) {
                int col = bn + wn + j * 8 + t * 2;
                *(__half2*)&Ch[(size_t)row * N + col] =
                    __floats2half2_rn(acc[i][j][0], acc[i][j][1]);
                *(__half2*)&Ch[(size_t)(row + 8) * N + col] =
                    __floats2half2_rn(acc[i][j][2], acc[i][j][3]);
            }
        }
    } else {
        float* C = bufptr(Ctag) + (size_t)blockIdx.z * M * N;
#pragma unroll
        for (int i = 0; i < 4; i++) {
            int row = bm + wm + i * 16 + g;
#pragma unroll
            for (int j = 0; j < 8; j++) {
                int col = bn + wn + j * 8 + t * 2;
                *(float2*)&C[(size_t)row * N + col] = make_float2(acc[i][j][0], acc[i][j][1]);
                *(float2*)&C[(size_t)(row + 8) * N + col] =
                    make_float2(acc[i][j][2], acc[i][j][3]);
            }
        }
    }
}

// ---------------- fc1 split-K reduce + bias + relu ----------------
__global__ void k_fcreduce(const float* __restrict__ bias) {
    int i = blockIdx.x * blockDim.x + threadIdx.x;
    if (i >= 512 * 512) return;
    float s = bias[i & 511];
#pragma unroll
    for (int p = 0; p < FC1_SPLITS; p++) s += g_fcp[p * 512 * 512 + i];
    g_fc1[i] = s > 0.f ? s : 0.f;
}

// ---------------- small GEMM with bias(+relu) (fc2, fp32 SIMT) ---------------
template <bool RELU>
__global__ __launch_bounds__(256) void k_gemm64(int Atag, const float* __restrict__ B,
                                                const float* __restrict__ bias, int Ctag,
                                                int M, int N, int K) {
    const float* A = bufptr(Atag);
    float* C = bufptr(Ctag);
    __shared__ float As[16][64];
    __shared__ float Bs[16][64];
    int tid = threadIdx.x;
    int tx = tid & 15, ty = tid >> 4;
    int bm = blockIdx.y * 64, bn = blockIdx.x * 64;
    float acc[4][4];
#pragma unroll
    for (int r = 0; r < 4; r++)
#pragma unroll
        for (int c = 0; c < 4; c++) acc[r][c] = 0.f;

    for (int kt = 0; kt < K; kt += 16) {
        {
            int arow = tid >> 2, ak4 = tid & 3;
            float4 va = *(const float4*)&A[(size_t)(bm + arow) * K + kt + ak4 * 4];
            As[ak4 * 4 + 0][arow] = va.x;
            As[ak4 * 4 + 1][arow] = va.y;
            As[ak4 * 4 + 2][arow] = va.z;
            As[ak4 * 4 + 3][arow] = va.w;
            int brow = tid >> 4, bc4 = tid & 15;
            float4 vb = *(const float4*)&B[(size_t)(kt + brow) * N + bn + bc4 * 4];
            *(float4*)&Bs[brow][bc4 * 4] = vb;
        }
        __syncthreads();
#pragma unroll
        for (int kk = 0; kk < 16; kk++) {
            float a[4], b[4];
            *(float4*)a = *(const float4*)&As[kk][ty * 4];
            *(float4*)b = *(const float4*)&Bs[kk][tx * 4];
#pragma unroll
            for (int r = 0; r < 4; r++)
#pragma unroll
                for (int c = 0; c < 4; c++) acc[r][c] += a[r] * b[c];
        }
        __syncthreads();
    }
#pragma unroll
    for (int r = 0; r < 4; r++) {
        int m = bm + ty * 4 + r;
#pragma unroll
        for (int c = 0; c < 4; c++) {
            int n = bn + tx * 4 + c;
            float v = acc[r][c] + bias[n];
            if (RELU) v = v > 0.f ? v : 0.f;
            C[(size_t)m * N + n] = v;
        }
    }
}

// ---------------- layer-1 alpha precompute ----------------
__global__ void k_wa(const float* __restrict__ W1, const float* __restrict__ as1,
                     const float* __restrict__ ad1) {
    int w = (blockIdx.x * blockDim.x + threadIdx.x) >> 5;
    int lane = threadIdx.x & 31;
    if (w >= HEADS1 * 128) return;
    int h = w >> 7, k = w & 127;
    const float* wr = W1 + (size_t)k * HC1 + h * 512;
    const float* sp = as1 + h * 512;
    const float* dp = ad1 + h * 512;
    float s1 = 0.f, s2 = 0.f;
    for (int c = lane; c < 512; c += 32) {
        float wv = wr[c];
        s1 += wv * sp[c];
        s2 += wv * dp[c];
    }
#pragma unroll
    for (int o = 16; o; o >>= 1) {
        s1 += __shfl_down_sync(0xffffffffu, s1, o);
        s2 += __shfl_down_sync(0xffffffffu, s2, o);
    }
    if (lane == 0) {
        g_was[h * 128 + k] = s1;
        g_wad[h * 128 + k] = s2;
    }
}

__global__ void k_alphax(const float* __restrict__ x) {
    int gw = (blockIdx.x * blockDim.x + threadIdx.x) >> 5;
    int lane = threadIdx.x & 31;
    if (gw >= NN * HEADS1) return;
    int n = gw >> 3, h = gw & 7;
    const float* xr = x + (size_t)n * 128;
    const float* ws = g_was + h * 128;
    const float* wd = g_wad + h * 128;
    float s1 = 0.f, s2 = 0.f;
#pragma unroll
    for (int i = 0; i < 4; i++) {
        int k = lane + i * 32;
        float v = xr[k];
        s1 += v * ws[k];
        s2 += v * wd[k];
    }
#pragma unroll
    for (int o = 16; o; o >>= 1) {
        s1 += __shfl_down_sync(0xffffffffu, s1, o);
        s2 += __shfl_down_sync(0xffffffffu, s2, o);
    }
    if (lane == 0) {
        g_as[gw] = s1;
        g_ad[gw] = s2;
    }
}

// ---------------- layer-2: reduce split-K -> h2 fp16, + dots ------------
__global__ void k_alpha2_red(const float* __restrict__ a_s, const float* __restrict__ a_d) {
    int gw = (blockIdx.x * blockDim.x + threadIdx.x) >> 5;
    int lane = threadIdx.x & 31;
    if (gw >= NN) return;
    const float* p0 = g_gp2 + (size_t)gw * HC2;
    const float* p1 = g_gp2 + (size_t)NN * HC2 + (size_t)gw * HC2;
    __half* hr = g_h2h + (size_t)gw * HC2;
    float s1 = 0.f, s2 = 0.f;
    for (int c = lane; c < HC2; c += 32) {
        float v = p0[c] + p1[c];
        hr[c] = __float2half(v);
        s1 += v * a_s[c];
        s2 += v * a_d[c];
    }
#pragma unroll
    for (int o = 16; o; o >>= 1) {
        s1 += __shfl_down_sync(0xffffffffu, s1, o);
        s2 += __shfl_down_sync(0xffffffffu, s2, o);
    }
    if (lane == 0) {
        g_as[gw] = s1;
        g_ad[gw] = s2;
    }
}

// ---------------- fused CSR edge softmax ----------------
template <int H, int NPB>
__global__ void k_softmax() {
    int wid = threadIdx.x >> 5, lane = threadIdx.x & 31;
    int n = blockIdx.x * NPB + wid / H;
    int hd = wid % H;
    int beg = g_rowptr[n], end = g_rowptr[n + 1];
    float adv = g_ad[n * H + hd];

    float mx = -1e30f;
    for (int i = beg + lane; i < end; i += 32) {
        int eid = g_eids[i];
        float v = g_as[g_srcv[eid] * H + hd] + adv;
        v = v > 0.f ? v : 0.2f * v;
        mx = fmaxf(mx, v);
    }
#pragma unroll
    for (int o = 16; o; o >>= 1) mx = fmaxf(mx, __shfl_xor_sync(0xffffffffu, mx, o));

    float s = 0.f;
    for (int i = beg + lane; i < end; i += 32) {
        int eid = g_eids[i];
        float v = g_as[g_srcv[eid] * H + hd] + adv;
        v = v > 0.f ? v : 0.2f * v;
        float e = expf(v - mx);
        g_eexp[eid * H + hd] = e;
        s += e;
    }
#pragma unroll
    for (int o = 16; o; o >>= 1) s += __shfl_xor_sync(0xffffffffu, s, o);
    float inv = 1.f / s;

    for (int i = beg + lane; i < end; i += 32) {
        int eid = g_eids[i];
        g_eexp[eid * H + hd] *= inv;
    }
}

// ---------------- layer-1 CSR aggregate (fp16 h, fp16 out) ----------------
__global__ __launch_bounds__(256) void k_agg1(const float* __restrict__ bias) {
    int n = blockIdx.x, tid = threadIdx.x;
    int c0 = tid * 16, head = tid >> 5;
    int beg = g_rowptr[n], end = g_rowptr[n + 1];
    float acc[16];
#pragma unroll
    for (int j = 0; j < 16; j++) acc[j] = 0.f;

    for (int idx = beg; idx < end; ++idx) {
        int eid = g_eids[idx];
        int src = g_srcv[eid];
        float al = g_eexp[eid * 8 + head];
        const uint4* hp = (const uint4*)(g_h1h + (size_t)src * HC1 + c0);
        uint4 u0 = hp[0], u1 = hp[1];
        unsigned w[8] = {u0.x, u0.y, u0.z, u0.w, u1.x, u1.y, u1.z, u1.w};
#pragma unroll
        for (int j = 0; j < 8; j++) {
            float2 f = __half22float2(*(__half2*)&w[j]);
            acc[2 * j] += al * f.x;
            acc[2 * j + 1] += al * f.y;
        }
    }
    unsigned ow[8];
#pragma unroll
    for (int j = 0; j < 8; j++) {
        float v0 = acc[2 * j] + bias[c0 + 2 * j];
        float v1 = acc[2 * j + 1] + bias[c0 + 2 * j + 1];
        v0 = v0 > 0.f ? v0 : 0.f;
        v1 = v1 > 0.f ? v1 : 0.f;
        __half2 p = __floats2half2_rn(v0, v1);
        ow[j] = *(unsigned*)&p;
    }
    uint4* op = (uint4*)(g_o1h + (size_t)n * HC1 + c0);
    op[0] = make_uint4(ow[0], ow[1], ow[2], ow[3]);
    op[1] = make_uint4(ow[4], ow[5], ow[6], ow[7]);
}

// ---------------- layer-2 CSR aggregate (fp16 h, fp16 out) ----------------
__global__ __launch_bounds__(256) void k_agg2(const float* __restrict__ bias) {
    int n = blockIdx.x, tid = threadIdx.x;
    int c0 = tid * 2;
    int beg = g_rowptr[n], end = g_rowptr[n + 1];
    float a0 = 0.f, a1 = 0.f;
    for (int idx = beg; idx < end; ++idx) {
        int eid = g_eids[idx];
        int src = g_srcv[eid];
        float al = g_eexp[eid];
        float2 f = __half22float2(*(const __half2*)(g_h2h + (size_t)src * HC2 + c0));
        a0 += al * f.x;
        a1 += al * f.y;
    }
    float v0 = a0 + bias[c0], v1 = a1 + bias[c0 + 1];
    v0 = v0 > 0.f ? v0 : 0.f;
    v1 = v1 > 0.f ? v1 : 0.f;
    *(__half2*)(g_o2h + (size_t)n * HC2 + c0) = __floats2half2_rn(v0, v1);
}

// ---------------- fc3 ----------------
__global__ void k_fc3(int Atag, const float* __restrict__ W,
                      const float* __restrict__ b, float* __restrict__ out) {
    const float* A = bufptr(Atag);
    int i = blockIdx.x * blockDim.x + threadIdx.x;
    if (i >= 512 * 10) return;
    int m = i / 10, n = i - m * 10;
    float s = b[n];
#pragma unroll 8
    for (int k = 0; k < 128; k++) s += A[m * 128 + k] * W[k * 10 + n];
    out[i] = s;
}

extern "C" void kernel_launch(void* const* d_in, const int* in_sizes, int n_in,
                              void* d_out, int out_size) {
    const float* x = (const float*)d_in[0];
    const int* ei_raw = (const int*)d_in[1];
    const float* W1 = (const float*)d_in[3];
    const float* as1 = (const float*)d_in[4];
    const float* ad1 = (const float*)d_in[5];
    const float* b1 = (const float*)d_in[6];
    const float* W2 = (const float*)d_in[7];
    const float* as2 = (const float*)d_in[8];
    const float* ad2 = (const float*)d_in[9];
    const float* b2 = (const float*)d_in[10];
    const float* fc1w = (const float*)d_in[11];
    const float* fc1b = (const float*)d_in[12];
    const float* fc2w = (const float*)d_in[13];
    const float* fc2b = (const float*)d_in[14];
    const float* fc3w = (const float*)d_in[15];
    const float* fc3b = (const float*)d_in[16];
    float* out = (float*)d_out;

    // ---- CSR build + straight converts ----
    k_detect<<<1, 1024>>>(ei_raw);
    k_cvt<<<(NN * 128 / 8 + 255) / 256, 256>>>(x, H_XH, NN * 128);
    k_cvt<<<(128 * HC1 / 8 + 255) / 256, 256>>>(W1, H_W1, 128 * HC1);
    k_cvt<<<(HC1 * HC2 / 8 + 255) / 256, 256>>>(W2, H_W2, HC1 * HC2);
    k_cvt<<<(HC1 * 512 / 8 + 255) / 256, 256>>>(fc1w, H_FW, HC1 * 512);
    k_wa<<<(HEADS1 * 128) / 8, 256>>>(W1, as1, ad1);
    k_convert<<<(ET + 255) / 256, 256>>>(ei_raw);
    k_scan<<<1, 1024>>>();
    k_scatter<<<(ET + 255) / 256, 256>>>();

    // ---- layer 1 ----
    k_mm_h<true><<<dim3(HC1 / 128, NN / 128, 1), 128>>>(H_XH, H_W1, H_H1, NN, HC1, 128,
                                                        128, HC1);
    k_alphax<<<(NN * HEADS1) / 8, 256>>>(x);
    k_softmax<HEADS1, 1><<<NN, 256>>>();
    k_agg1<<<NN, 256>>>(b1);

    // ---- layer 2: split-K=2 ----
    k_mm_h<false><<<dim3(HC2 / 128, NN / 128, 2), 128>>>(H_O1, H_W2, B_GP2, NN, HC2,
                                                         HC1 / 2, HC1, HC2);
    k_alpha2_red<<<(NN * 32 + 255) / 256, 256>>>(as2, ad2);
    k_softmax<1, 8><<<NN / 8, 256>>>();
    k_agg2<<<NN, 256>>>(b2);

    // ---- MLP head ----
    k_mm_h<false><<<dim3(512 / 128, 512 / 128, FC1_SPLITS), 128>>>(
        H_O2, H_FW, B_FCP, 512, 512, HC1 / FC1_SPLITS, HC1, 512);
    k_fcreduce<<<(512 * 512 + 255) / 256, 256>>>(fc1b);
    k_gemm64<true><<<dim3(128 / 64, 512 / 64), 256>>>(B_FC1, fc2w, fc2b, B_FC2, 512, 128, 512);
    k_fc3<<<(512 * 10 + 255) / 256, 256>>>(B_FC2, fc3w, fc3b, out);
}

// round 15
// speedup vs baseline: 4.1493x; 1.0846x over previous
#include <cuda_runtime.h>
#include <cuda_fp16.h>
#include <math.h>

#define NN 4096
#define EE 32768
#define ET (EE + NN)
#define HEADS1 8
#define HC1 4096
#define HC2 512
#define FC1_SPLITS 8

// ---------------- scratch (device globals) ----------------
__device__ __half g_xh[NN * 128];
__device__ __half g_w1h[(size_t)128 * HC1];
__device__ __half g_w2h[(size_t)HC1 * HC2];
__device__ __half g_fw1h[(size_t)HC1 * 512];
__device__ __half g_h1h[(size_t)NN * HC1];
__device__ __half g_o1h[(size_t)NN * HC1];
__device__ __half g_h2h[NN * HC2];
__device__ __half g_o2h[NN * HC2];
__device__ float g_as[NN * HEADS1];
__device__ float g_ad[NN * HEADS1];
__device__ float g_was[HEADS1 * 128];
__device__ float g_wad[HEADS1 * 128];
__device__ float g_eexp[(size_t)ET * HEADS1];
__device__ int g_rowptr[NN + 1];
__device__ int g_counts[NN];
__device__ int g_cursor[NN];
__device__ int g_eids[ET];
__device__ int g_srcv[ET];
__device__ int g_dstv[ET];
__device__ int g_flag64;
__device__ float g_fc1[512 * 512];
__device__ float g_fc2[512 * 128];
__device__ float g_fcp[FC1_SPLITS * 512 * 512];
__device__ float g_gp2[2 * NN * HC2];

// float buffer tags
#define B_FC1 0
#define B_FC2 1
#define B_FCP 2
#define B_GP2 3
__device__ __forceinline__ float* bufptr(int b) {
    switch (b) {
        case B_FC1: return g_fc1;
        case B_FC2: return g_fc2;
        case B_FCP: return g_fcp;
        default: return g_gp2;
    }
}
// half buffer tags
#define H_XH 0
#define H_W1 1
#define H_W2 2
#define H_FW 3
#define H_H1 4
#define H_O1 5
#define H_H2 6
#define H_O2 7
__device__ __forceinline__ __half* hbuf(int b) {
    switch (b) {
        case H_XH: return g_xh;
        case H_W1: return g_w1h;
        case H_W2: return g_w2h;
        case H_FW: return g_fw1h;
        case H_H1: return g_h1h;
        case H_O1: return g_o1h;
        case H_H2: return g_h2h;
        default: return g_o2h;
    }
}

// ------------- mma + ldmatrix + cp.async helpers -------------
__device__ __forceinline__ void mma_f16(float* d, unsigned a0, unsigned a1, unsigned a2,
                                        unsigned a3, unsigned b0, unsigned b1) {
    asm volatile(
        "mma.sync.aligned.m16n8k16.row.col.f32.f16.f16.f32 "
        "{%0,%1,%2,%3}, {%4,%5,%6,%7}, {%8,%9}, {%0,%1,%2,%3};\n"
        : "+f"(d[0]), "+f"(d[1]), "+f"(d[2]), "+f"(d[3])
        : "r"(a0), "r"(a1), "r"(a2), "r"(a3), "r"(b0), "r"(b1));
}
__device__ __forceinline__ void ldsm4(unsigned* r, const void* p) {
    unsigned a = (unsigned)__cvta_generic_to_shared(p);
    asm volatile("ldmatrix.sync.aligned.m8n8.x4.shared.b16 {%0,%1,%2,%3}, [%4];"
                 : "=r"(r[0]), "=r"(r[1]), "=r"(r[2]), "=r"(r[3]) : "r"(a));
}
__device__ __forceinline__ void ldsm4t(unsigned* r, const void* p) {
    unsigned a = (unsigned)__cvta_generic_to_shared(p);
    asm volatile("ldmatrix.sync.aligned.m8n8.x4.trans.shared.b16 {%0,%1,%2,%3}, [%4];"
                 : "=r"(r[0]), "=r"(r[1]), "=r"(r[2]), "=r"(r[3]) : "r"(a));
}
__device__ __forceinline__ void cpasync16(void* s, const void* g) {
    unsigned sa = (unsigned)__cvta_generic_to_shared(s);
    asm volatile("cp.async.ca.shared.global [%0], [%1], 16;\n" ::"r"(sa), "l"(g));
}
__device__ __forceinline__ void cp_commit() { asm volatile("cp.async.commit_group;\n"); }
__device__ __forceinline__ void cp_wait1() { asm volatile("cp.async.wait_group 1;\n"); }
__device__ __forceinline__ void cp_wait0() { asm volatile("cp.async.wait_group 0;\n"); }

// ---------------- dtype probe + CSR zero ----------
__global__ void k_detect(const int* __restrict__ raw) {
    int t = threadIdx.x;
    for (int i = t; i < NN; i += 1024) {
        g_counts[i] = 0;
        g_cursor[i] = 0;
    }
    __shared__ int s_or;
    if (t == 0) s_or = 0;
    __syncthreads();
    int acc = 0;
    for (int i = t; i < 8192; i += 1024) acc |= raw[2 * i + 1];
    if (acc) atomicOr(&s_or, 1);
    __syncthreads();
    if (t == 0) g_flag64 = (s_or == 0) ? 1 : 0;
}

__global__ void k_convert(const int* __restrict__ raw) {
    int i = blockIdx.x * blockDim.x + threadIdx.x;
    if (i >= ET) return;
    int s, d;
    if (i < EE) {
        if (g_flag64) {
            s = raw[2 * i];
            d = raw[2 * (EE + i)];
        } else {
            s = raw[i];
            d = raw[EE + i];
        }
    } else {
        s = d = i - EE;
    }
    g_srcv[i] = s;
    g_dstv[i] = d;
    atomicAdd(&g_counts[d], 1);
}

__global__ void k_scan() {
    __shared__ int s[1024];
    int t = threadIdx.x;
    int c0 = g_counts[4 * t + 0];
    int c1 = g_counts[4 * t + 1];
    int c2 = g_counts[4 * t + 2];
    int c3 = g_counts[4 * t + 3];
    int sum = c0 + c1 + c2 + c3;
    s[t] = sum;
    __syncthreads();
    for (int off = 1; off < 1024; off <<= 1) {
        int v = (t >= off) ? s[t - off] : 0;
        __syncthreads();
        s[t] += v;
        __syncthreads();
    }
    int excl = s[t] - sum;
    g_rowptr[4 * t + 0] = excl;
    g_rowptr[4 * t + 1] = excl + c0;
    g_rowptr[4 * t + 2] = excl + c0 + c1;
    g_rowptr[4 * t + 3] = excl + c0 + c1 + c2;
    if (t == 1023) g_rowptr[NN] = excl + sum;
}

__global__ void k_scatter() {
    int i = blockIdx.x * blockDim.x + threadIdx.x;
    if (i >= ET) return;
    int dst = g_dstv[i];
    int pos = g_rowptr[dst] + atomicAdd(&g_cursor[dst], 1);
    g_eids[pos] = i;
}

// ---------------- merged fp32->fp16 converts (x, W1, W2, fc1w) ----------------
#define CVT_S0 (NN * 128)
#define CVT_S1 (128 * HC1)
#define CVT_S2 (HC1 * HC2)
#define CVT_S3 (HC1 * 512)
#define CVT_TOT (CVT_S0 + CVT_S1 + CVT_S2 + CVT_S3)
__global__ void k_cvt_all(const float* __restrict__ x, const float* __restrict__ w1,
                          const float* __restrict__ w2, const float* __restrict__ fw) {
    int gi = (blockIdx.x * blockDim.x + threadIdx.x) * 16;
    if (gi >= CVT_TOT) return;
    const float* src;
    __half* dst;
    int i = gi;
    if (i < CVT_S0) {
        src = x; dst = g_xh;
    } else if ((i -= CVT_S0) < CVT_S1) {
        src = w1; dst = g_w1h;
    } else if ((i -= CVT_S1) < CVT_S2) {
        src = w2; dst = g_w2h;
    } else {
        i -= CVT_S2;
        src = fw; dst = g_fw1h;
    }
#pragma unroll
    for (int u = 0; u < 2; u++) {
        float4 a = *(const float4*)&src[i + u * 8];
        float4 b = *(const float4*)&src[i + u * 8 + 4];
        __half2 h0 = __floats2half2_rn(a.x, a.y);
        __half2 h1 = __floats2half2_rn(a.z, a.w);
        __half2 h2 = __floats2half2_rn(b.x, b.y);
        __half2 h3 = __floats2half2_rn(b.z, b.w);
        *(uint4*)&dst[i + u * 8] = make_uint4(*(unsigned*)&h0, *(unsigned*)&h1,
                                              *(unsigned*)&h2, *(unsigned*)&h3);
    }
}

// ---------------- fp16 GEMM: K-step 32, ldmatrix frags ----------------
// C[M,N](+z*M*N) = A[M][lda] @ B[K][ldbN] over rows koff..koff+Kc of B
template <bool OUTH>
__global__ __launch_bounds__(128) void k_mm_h(int Atag, int Btag, int Ctag,
                                              int M, int N, int Kc, int lda, int ldbN) {
    const __half* Ag = hbuf(Atag);
    const __half* Bg = hbuf(Btag);
    int koff = blockIdx.z * Kc;
    __shared__ __half As[2][128][40];   // [m][k32] 80B rows: aligned + bank-spread
    __shared__ __half Bs[2][32][136];   // [k32][n] 272B rows
    int tid = threadIdx.x;
    int lane = tid & 31, wid = tid >> 5;
    int wm = (wid >> 1) * 64, wn = (wid & 1) * 64;
    int bm = blockIdx.y * 128, bn = blockIdx.x * 128;
    int g = lane >> 2, t = lane & 3;

    float acc[4][8][4];
#pragma unroll
    for (int i = 0; i < 4; i++)
#pragma unroll
        for (int j = 0; j < 8; j++)
#pragma unroll
            for (int r = 0; r < 4; r++) acc[i][j][r] = 0.f;

    const int NIT = Kc / 32;
    int l16 = lane & 15, lhi = lane >> 4;
#define LOADH(it, buf)                                                                   \
    {                                                                                    \
        int kt = koff + (it) * 32;                                                       \
        _Pragma("unroll") for (int i = 0; i < 4; i++) {                                  \
            int idx = tid + i * 128, r = idx >> 2, ch = idx & 3;                         \
            cpasync16(&As[buf][r][ch * 8], Ag + (size_t)(bm + r) * lda + kt + ch * 8);   \
        }                                                                                \
        _Pragma("unroll") for (int i = 0; i < 4; i++) {                                  \
            int idx = tid + i * 128, r = idx >> 4, ch = idx & 15;                        \
            cpasync16(&Bs[buf][r][ch * 8], Bg + (size_t)(kt + r) * ldbN + bn + ch * 8);  \
        }                                                                                \
    }

    LOADH(0, 0);
    cp_commit();

    for (int it = 0; it < NIT; it++) {
        int cb = it & 1;
        if (it + 1 < NIT) {
            LOADH(it + 1, cb ^ 1);
            cp_commit();
            cp_wait1();
        } else {
            cp_wait0();
        }
        __syncthreads();
#pragma unroll
        for (int ks = 0; ks < 2; ks++) {
            unsigned af[4][4], bf[4][4];
#pragma unroll
            for (int i = 0; i < 4; i++)
                ldsm4(af[i], &As[cb][wm + i * 16 + l16][ks * 16 + lhi * 8]);
#pragma unroll
            for (int j4 = 0; j4 < 4; j4++)
                ldsm4t(bf[j4], &Bs[cb][ks * 16 + l16][wn + j4 * 16 + lhi * 8]);
#pragma unroll
            for (int i = 0; i < 4; i++)
#pragma unroll
                for (int j4 = 0; j4 < 4; j4++) {
                    mma_f16(acc[i][2 * j4], af[i][0], af[i][1], af[i][2], af[i][3],
                            bf[j4][0], bf[j4][1]);
                    mma_f16(acc[i][2 * j4 + 1], af[i][0], af[i][1], af[i][2], af[i][3],
                            bf[j4][2], bf[j4][3]);
                }
        }
        __syncthreads();
    }
    if (OUTH) {
        __half* Ch = hbuf(Ctag);
#pragma unroll
        for (int i = 0; i < 4; i++) {
            int row = bm + wm + i * 16 + g;
#pragma unroll
            for (int j = 0; j < 8; j++) {
                int col = bn + wn + j * 8 + t * 2;
                *(__half2*)&Ch[(size_t)row * N + col] =
                    __floats2half2_rn(acc[i][j][0], acc[i][j][1]);
                *(__half2*)&Ch[(size_t)(row + 8) * N + col] =
                    __floats2half2_rn(acc[i][j][2], acc[i][j][3]);
            }
        }
    } else {
        float* C = bufptr(Ctag) + (size_t)blockIdx.z * M * N;
#pragma unroll
        for (int i = 0; i < 4; i++) {
            int row = bm + wm + i * 16 + g;
#pragma unroll
            for (int j = 0; j < 8; j++) {
                int col = bn + wn + j * 8 + t * 2;
                *(float2*)&C[(size_t)row * N + col] = make_float2(acc[i][j][0], acc[i][j][1]);
                *(float2*)&C[(size_t)(row + 8) * N + col] =
                    make_float2(acc[i][j][2], acc[i][j][3]);
            }
        }
    }
}

// ---------------- fc1 split-K reduce + bias + relu ----------------
__global__ void k_fcreduce(const float* __restrict__ bias) {
    int i = blockIdx.x * blockDim.x + threadIdx.x;
    if (i >= 512 * 512) return;
    float s = bias[i & 511];
#pragma unroll
    for (int p = 0; p < FC1_SPLITS; p++) s += g_fcp[p * 512 * 512 + i];
    g_fc1[i] = s > 0.f ? s : 0.f;
}

// ---------------- small GEMM with bias(+relu) (fc2, fp32 SIMT) ---------------
template <bool RELU>
__global__ __launch_bounds__(256) void k_gemm64(int Atag, const float* __restrict__ B,
                                                const float* __restrict__ bias, int Ctag,
                                                int M, int N, int K) {
    const float* A = bufptr(Atag);
    float* C = bufptr(Ctag);
    __shared__ float As[16][64];
    __shared__ float Bs[16][64];
    int tid = threadIdx.x;
    int tx = tid & 15, ty = tid >> 4;
    int bm = blockIdx.y * 64, bn = blockIdx.x * 64;
    float acc[4][4];
#pragma unroll
    for (int r = 0; r < 4; r++)
#pragma unroll
        for (int c = 0; c < 4; c++) acc[r][c] = 0.f;

    for (int kt = 0; kt < K; kt += 16) {
        {
            int arow = tid >> 2, ak4 = tid & 3;
            float4 va = *(const float4*)&A[(size_t)(bm + arow) * K + kt + ak4 * 4];
            As[ak4 * 4 + 0][arow] = va.x;
            As[ak4 * 4 + 1][arow] = va.y;
            As[ak4 * 4 + 2][arow] = va.z;
            As[ak4 * 4 + 3][arow] = va.w;
            int brow = tid >> 4, bc4 = tid & 15;
            float4 vb = *(const float4*)&B[(size_t)(kt + brow) * N + bn + bc4 * 4];
            *(float4*)&Bs[brow][bc4 * 4] = vb;
        }
        __syncthreads();
#pragma unroll
        for (int kk = 0; kk < 16; kk++) {
            float a[4], b[4];
            *(float4*)a = *(const float4*)&As[kk][ty * 4];
            *(float4*)b = *(const float4*)&Bs[kk][tx * 4];
#pragma unroll
            for (int r = 0; r < 4; r++)
#pragma unroll
                for (int c = 0; c < 4; c++) acc[r][c] += a[r] * b[c];
        }
        __syncthreads();
    }
#pragma unroll
    for (int r = 0; r < 4; r++) {
        int m = bm + ty * 4 + r;
#pragma unroll
        for (int c = 0; c < 4; c++) {
            int n = bn + tx * 4 + c;
            float v = acc[r][c] + bias[n];
            if (RELU) v = v > 0.f ? v : 0.f;
            C[(size_t)m * N + n] = v;
        }
    }
}

// ---------------- layer-1 alpha precompute ----------------
__global__ void k_wa(const float* __restrict__ W1, const float* __restrict__ as1,
                     const float* __restrict__ ad1) {
    int w = (blockIdx.x * blockDim.x + threadIdx.x) >> 5;
    int lane = threadIdx.x & 31;
    if (w >= HEADS1 * 128) return;
    int h = w >> 7, k = w & 127;
    const float* wr = W1 + (size_t)k * HC1 + h * 512;
    const float* sp = as1 + h * 512;
    const float* dp = ad1 + h * 512;
    float s1 = 0.f, s2 = 0.f;
    for (int c = lane; c < 512; c += 32) {
        float wv = wr[c];
        s1 += wv * sp[c];
        s2 += wv * dp[c];
    }
#pragma unroll
    for (int o = 16; o; o >>= 1) {
        s1 += __shfl_down_sync(0xffffffffu, s1, o);
        s2 += __shfl_down_sync(0xffffffffu, s2, o);
    }
    if (lane == 0) {
        g_was[h * 128 + k] = s1;
        g_wad[h * 128 + k] = s2;
    }
}

__global__ void k_alphax(const float* __restrict__ x) {
    int gw = (blockIdx.x * blockDim.x + threadIdx.x) >> 5;
    int lane = threadIdx.x & 31;
    if (gw >= NN * HEADS1) return;
    int n = gw >> 3, h = gw & 7;
    const float* xr = x + (size_t)n * 128;
    const float* ws = g_was + h * 128;
    const float* wd = g_wad + h * 128;
    float s1 = 0.f, s2 = 0.f;
#pragma unroll
    for (int i = 0; i < 4; i++) {
        int k = lane + i * 32;
        float v = xr[k];
        s1 += v * ws[k];
        s2 += v * wd[k];
    }
#pragma unroll
    for (int o = 16; o; o >>= 1) {
        s1 += __shfl_down_sync(0xffffffffu, s1, o);
        s2 += __shfl_down_sync(0xffffffffu, s2, o);
    }
    if (lane == 0) {
        g_as[gw] = s1;
        g_ad[gw] = s2;
    }
}

// ---------------- layer-2: reduce split-K -> h2 fp16, + dots ------------
__global__ void k_alpha2_red(const float* __restrict__ a_s, const float* __restrict__ a_d) {
    int gw = (blockIdx.x * blockDim.x + threadIdx.x) >> 5;
    int lane = threadIdx.x & 31;
    if (gw >= NN) return;
    const float* p0 = g_gp2 + (size_t)gw * HC2;
    const float* p1 = g_gp2 + (size_t)NN * HC2 + (size_t)gw * HC2;
    __half* hr = g_h2h + (size_t)gw * HC2;
    float s1 = 0.f, s2 = 0.f;
    for (int c = lane; c < HC2; c += 32) {
        float v = p0[c] + p1[c];
        hr[c] = __float2half(v);
        s1 += v * a_s[c];
        s2 += v * a_d[c];
    }
#pragma unroll
    for (int o = 16; o; o >>= 1) {
        s1 += __shfl_down_sync(0xffffffffu, s1, o);
        s2 += __shfl_down_sync(0xffffffffu, s2, o);
    }
    if (lane == 0) {
        g_as[gw] = s1;
        g_ad[gw] = s2;
    }
}

// ---------------- fused CSR edge softmax ----------------
template <int H, int NPB>
__global__ void k_softmax() {
    int wid = threadIdx.x >> 5, lane = threadIdx.x & 31;
    int n = blockIdx.x * NPB + wid / H;
    int hd = wid % H;
    int beg = g_rowptr[n], end = g_rowptr[n + 1];
    float adv = g_ad[n * H + hd];

    float mx = -1e30f;
    for (int i = beg + lane; i < end; i += 32) {
        int eid = g_eids[i];
        float v = g_as[g_srcv[eid] * H + hd] + adv;
        v = v > 0.f ? v : 0.2f * v;
        mx = fmaxf(mx, v);
    }
#pragma unroll
    for (int o = 16; o; o >>= 1) mx = fmaxf(mx, __shfl_xor_sync(0xffffffffu, mx, o));

    float s = 0.f;
    for (int i = beg + lane; i < end; i += 32) {
        int eid = g_eids[i];
        float v = g_as[g_srcv[eid] * H + hd] + adv;
        v = v > 0.f ? v : 0.2f * v;
        float e = expf(v - mx);
        g_eexp[eid * H + hd] = e;
        s += e;
    }
#pragma unroll
    for (int o = 16; o; o >>= 1) s += __shfl_xor_sync(0xffffffffu, s, o);
    float inv = 1.f / s;

    for (int i = beg + lane; i < end; i += 32) {
        int eid = g_eids[i];
        g_eexp[eid * H + hd] *= inv;
    }
}

// ---------------- layer-1 CSR aggregate (fp16 h, fp16 out) ----------------
__global__ __launch_bounds__(256) void k_agg1(const float* __restrict__ bias) {
    int n = blockIdx.x, tid = threadIdx.x;
    int c0 = tid * 16, head = tid >> 5;
    int beg = g_rowptr[n], end = g_rowptr[n + 1];
    float acc[16];
#pragma unroll
    for (int j = 0; j < 16; j++) acc[j] = 0.f;

    for (int idx = beg; idx < end; ++idx) {
        int eid = g_eids[idx];
        int src = g_srcv[eid];
        float al = g_eexp[eid * 8 + head];
        const uint4* hp = (const uint4*)(g_h1h + (size_t)src * HC1 + c0);
        uint4 u0 = hp[0], u1 = hp[1];
        unsigned w[8] = {u0.x, u0.y, u0.z, u0.w, u1.x, u1.y, u1.z, u1.w};
#pragma unroll
        for (int j = 0; j < 8; j++) {
            float2 f = __half22float2(*(__half2*)&w[j]);
            acc[2 * j] += al * f.x;
            acc[2 * j + 1] += al * f.y;
        }
    }
    unsigned ow[8];
#pragma unroll
    for (int j = 0; j < 8; j++) {
        float v0 = acc[2 * j] + bias[c0 + 2 * j];
        float v1 = acc[2 * j + 1] + bias[c0 + 2 * j + 1];
        v0 = v0 > 0.f ? v0 : 0.f;
        v1 = v1 > 0.f ? v1 : 0.f;
        __half2 p = __floats2half2_rn(v0, v1);
        ow[j] = *(unsigned*)&p;
    }
    uint4* op = (uint4*)(g_o1h + (size_t)n * HC1 + c0);
    op[0] = make_uint4(ow[0], ow[1], ow[2], ow[3]);
    op[1] = make_uint4(ow[4], ow[5], ow[6], ow[7]);
}

// ---------------- layer-2 CSR aggregate (fp16 h, fp16 out) ----------------
__global__ __launch_bounds__(256) void k_agg2(const float* __restrict__ bias) {
    int n = blockIdx.x, tid = threadIdx.x;
    int c0 = tid * 2;
    int beg = g_rowptr[n], end = g_rowptr[n + 1];
    float a0 = 0.f, a1 = 0.f;
    for (int idx = beg; idx < end; ++idx) {
        int eid = g_eids[idx];
        int src = g_srcv[eid];
        float al = g_eexp[eid];
        float2 f = __half22float2(*(const __half2*)(g_h2h + (size_t)src * HC2 + c0));
        a0 += al * f.x;
        a1 += al * f.y;
    }
    float v0 = a0 + bias[c0], v1 = a1 + bias[c0 + 1];
    v0 = v0 > 0.f ? v0 : 0.f;
    v1 = v1 > 0.f ? v1 : 0.f;
    *(__half2*)(g_o2h + (size_t)n * HC2 + c0) = __floats2half2_rn(v0, v1);
}

// ---------------- fc3 ----------------
__global__ void k_fc3(int Atag, const float* __restrict__ W,
                      const float* __restrict__ b, float* __restrict__ out) {
    const float* A = bufptr(Atag);
    int i = blockIdx.x * blockDim.x + threadIdx.x;
    if (i >= 512 * 10) return;
    int m = i / 10, n = i - m * 10;
    float s = b[n];
#pragma unroll 8
    for (int k = 0; k < 128; k++) s += A[m * 128 + k] * W[k * 10 + n];
    out[i] = s;
}

extern "C" void kernel_launch(void* const* d_in, const int* in_sizes, int n_in,
                              void* d_out, int out_size) {
    const float* x = (const float*)d_in[0];
    const int* ei_raw = (const int*)d_in[1];
    const float* W1 = (const float*)d_in[3];
    const float* as1 = (const float*)d_in[4];
    const float* ad1 = (const float*)d_in[5];
    const float* b1 = (const float*)d_in[6];
    const float* W2 = (const float*)d_in[7];
    const float* as2 = (const float*)d_in[8];
    const float* ad2 = (const float*)d_in[9];
    const float* b2 = (const float*)d_in[10];
    const float* fc1w = (const float*)d_in[11];
    const float* fc1b = (const float*)d_in[12];
    const float* fc2w = (const float*)d_in[13];
    const float* fc2b = (const float*)d_in[14];
    const float* fc3w = (const float*)d_in[15];
    const float* fc3b = (const float*)d_in[16];
    float* out = (float*)d_out;

    // ---- CSR build + merged converts ----
    k_detect<<<1, 1024>>>(ei_raw);
    k_cvt_all<<<(CVT_TOT / 16 + 255) / 256, 256>>>(x, W1, W2, fc1w);
    k_wa<<<(HEADS1 * 128) / 8, 256>>>(W1, as1, ad1);
    k_convert<<<(ET + 255) / 256, 256>>>(ei_raw);
    k_scan<<<1, 1024>>>();
    k_scatter<<<(ET + 255) / 256, 256>>>();

    // ---- layer 1 ----
    k_mm_h<true><<<dim3(HC1 / 128, NN / 128, 1), 128>>>(H_XH, H_W1, H_H1, NN, HC1, 128,
                                                        128, HC1);
    k_alphax<<<(NN * HEADS1) / 8, 256>>>(x);
    k_softmax<HEADS1, 1><<<NN, 256>>>();
    k_agg1<<<NN, 256>>>(b1);

    // ---- layer 2: split-K=2 ----
    k_mm_h<false><<<dim3(HC2 / 128, NN / 128, 2), 128>>>(H_O1, H_W2, B_GP2, NN, HC2,
                                                         HC1 / 2, HC1, HC2);
    k_alpha2_red<<<(NN * 32 + 255) / 256, 256>>>(as2, ad2);
    k_softmax<1, 8><<<NN / 8, 256>>>();
    k_agg2<<<NN, 256>>>(b2);

    // ---- MLP head ----
    k_mm_h<false><<<dim3(512 / 128, 512 / 128, FC1_SPLITS), 128>>>(
        H_O2, H_FW, B_FCP, 512, 512, HC1 / FC1_SPLITS, HC1, 512);
    k_fcreduce<<<(512 * 512 + 255) / 256, 256>>>(fc1b);
    k_gemm64<true><<<dim3(128 / 64, 512 / 64), 256>>>(B_FC1, fc2w, fc2b, B_FC2, 512, 128, 512);
    k_fc3<<<(512 * 10 + 255) / 256, 256>>>(B_FC2, fc3w, fc3b, out);
}